// round 3
// baseline (speedup 1.0000x reference)
#include <cuda_runtime.h>
#include <math.h>

// Problem constants (fixed shapes)
#define BB 2
#define SS 2048
#define DD 2048
#define HH 32
#define GG 8
#define HD 64
#define KVD 512        // G*HD
#define MTOT (BB*SS)   // 4096 rows for all GEMMs

// Scratch (static device globals; no allocation allowed)
__device__ float g_q [BB*SS*DD];    // [B,S,H*HD]  33.5 MB
__device__ float g_k [BB*SS*KVD];   // [B,S,G*HD]   8.4 MB
__device__ float g_v [BB*SS*KVD];   //              8.4 MB
__device__ float g_ao[BB*SS*DD];    // attention out, [B,S,H*HD]

// ---------------------------------------------------------------------------
// GEMM + bias: C[M,N] = A[M,K] @ W[K,N] + bias[N]
// 128x128 tile, BK=8, 256 threads, 8x8 micro-tile per thread.
// Requires M%128==0, N%128==0, K%8==0, K%4==0 alignment (true for all calls).
// ---------------------------------------------------------------------------
__global__ void __launch_bounds__(256) gemm_bias_kernel(
    const float* __restrict__ A, const float* __restrict__ W,
    const float* __restrict__ bias, float* __restrict__ C,
    int M, int N, int K)
{
    __shared__ float As[8][132];   // transposed A tile, padded (conflict-free)
    __shared__ float Bs[8][128];

    const int tid = threadIdx.x;
    const int tx  = tid & 15;
    const int ty  = tid >> 4;
    const int row0 = blockIdx.y * 128;
    const int col0 = blockIdx.x * 128;

    float acc[8][8];
    #pragma unroll
    for (int i = 0; i < 8; i++)
        #pragma unroll
        for (int j = 0; j < 8; j++) acc[i][j] = 0.0f;

    // load mapping
    const int ar = tid >> 1;          // 0..127 (A row within tile)
    const int ak = (tid & 1) << 2;    // 0 or 4 (A k offset)
    const int bk = tid >> 5;          // 0..7   (B row within tile)
    const int bn = (tid & 31) << 2;   // 0..124 (B col offset)

    const float* Ap = A + (size_t)(row0 + ar) * K + ak;
    const float* Bp = W + (size_t)bk * N + col0 + bn;

    for (int kt = 0; kt < K; kt += 8) {
        const float4 av = *(const float4*)(Ap + kt);
        const float4 bv = *(const float4*)(Bp + (size_t)kt * N);
        __syncthreads();
        As[ak + 0][ar] = av.x;
        As[ak + 1][ar] = av.y;
        As[ak + 2][ar] = av.z;
        As[ak + 3][ar] = av.w;
        *(float4*)&Bs[bk][bn] = bv;
        __syncthreads();

        #pragma unroll
        for (int k = 0; k < 8; k++) {
            float a[8], b[8];
            *(float4*)(a)     = *(const float4*)&As[k][ty * 8];
            *(float4*)(a + 4) = *(const float4*)&As[k][ty * 8 + 4];
            *(float4*)(b)     = *(const float4*)&Bs[k][tx * 8];
            *(float4*)(b + 4) = *(const float4*)&Bs[k][tx * 8 + 4];
            #pragma unroll
            for (int i = 0; i < 8; i++)
                #pragma unroll
                for (int j = 0; j < 8; j++)
                    acc[i][j] = fmaf(a[i], b[j], acc[i][j]);
        }
    }

    const float* bp = bias + col0 + tx * 8;
    float bv0[8];
    #pragma unroll
    for (int j = 0; j < 8; j++) bv0[j] = bp[j];

    #pragma unroll
    for (int i = 0; i < 8; i++) {
        float* Cp = C + (size_t)(row0 + ty * 8 + i) * N + col0 + tx * 8;
        float4 o0, o1;
        o0.x = acc[i][0] + bv0[0]; o0.y = acc[i][1] + bv0[1];
        o0.z = acc[i][2] + bv0[2]; o0.w = acc[i][3] + bv0[3];
        o1.x = acc[i][4] + bv0[4]; o1.y = acc[i][5] + bv0[5];
        o1.z = acc[i][6] + bv0[6]; o1.w = acc[i][7] + bv0[7];
        *(float4*)Cp       = o0;
        *(float4*)(Cp + 4) = o1;
    }
}

// ---------------------------------------------------------------------------
// Fused causal GQA attention, flash style.
// Grid: (S/64, B*H). Block: 256 threads.
// Q: [B,S,H*HD], K/V: [B,S,G*HD], O: [B,S,H*HD]. 64x64 tiles, online softmax.
// ---------------------------------------------------------------------------
#define ATTN_SMEM_FLOATS (64*65 /*Qt*/ + 64*65 /*Kt*/ + 64*64 /*Vs*/ + 64*65 /*Ps*/)
#define ATTN_SMEM_BYTES  (ATTN_SMEM_FLOATS * 4)

__global__ void __launch_bounds__(256) attn_kernel(
    const float* __restrict__ Q, const float* __restrict__ Kg,
    const float* __restrict__ Vg, float* __restrict__ O)
{
    extern __shared__ float sm[];
    float* Qt = sm;                 // [64][65]  transposed: Qt[d][r]
    float* Kt = Qt + 64 * 65;       // [64][65]  transposed: Kt[d][c]
    float* Vs = Kt + 64 * 65;       // [64][64]  Vs[k][d]
    float* Ps = Vs + 64 * 64;       // [64][65]  Ps[r][k]

    const int tid = threadIdx.x;
    const int tx  = tid & 15;       // col group
    const int ty  = tid >> 4;       // row group
    const int qt  = blockIdx.x;
    const int bh  = blockIdx.y;
    const int b   = bh >> 5;
    const int h   = bh & 31;
    const int g   = h >> 2;         // group index (GS=4)
    const int q0  = qt * 64;

    const float* Qb = Q  + (size_t)(b * SS) * DD  + h * HD;
    const float* Kb = Kg + (size_t)(b * SS) * KVD + g * HD;
    const float* Vb = Vg + (size_t)(b * SS) * KVD + g * HD;

    // Load Q tile (64 rows x 64 dims), store transposed
    #pragma unroll
    for (int it = 0; it < 4; it++) {
        int idx = it * 256 + tid;
        int r = idx >> 4;
        int d = (idx & 15) << 2;
        float4 v = *(const float4*)(Qb + (size_t)(q0 + r) * DD + d);
        Qt[(d + 0) * 65 + r] = v.x;
        Qt[(d + 1) * 65 + r] = v.y;
        Qt[(d + 2) * 65 + r] = v.z;
        Qt[(d + 3) * 65 + r] = v.w;
    }

    float m[4], l[4], o[4][4];
    #pragma unroll
    for (int i = 0; i < 4; i++) {
        m[i] = -1e30f; l[i] = 0.0f;
        #pragma unroll
        for (int j = 0; j < 4; j++) o[i][j] = 0.0f;
    }

    const float scale = 0.125f;   // 1/sqrt(64)
    const int nkt = qt + 1;       // causal: only tiles at/below diagonal

    for (int t = 0; t < nkt; t++) {
        const int k0 = t * 64;
        __syncthreads();   // previous iteration done reading Kt/Vs/Ps

        // Load K tile transposed + V tile
        #pragma unroll
        for (int it = 0; it < 4; it++) {
            int idx = it * 256 + tid;
            int r = idx >> 4;
            int d = (idx & 15) << 2;
            float4 kv4 = *(const float4*)(Kb + (size_t)(k0 + r) * KVD + d);
            Kt[(d + 0) * 65 + r] = kv4.x;
            Kt[(d + 1) * 65 + r] = kv4.y;
            Kt[(d + 2) * 65 + r] = kv4.z;
            Kt[(d + 3) * 65 + r] = kv4.w;
            float4 vv = *(const float4*)(Vb + (size_t)(k0 + r) * KVD + d);
            *(float4*)&Vs[r * 64 + d] = vv;
        }
        __syncthreads();

        // S = Q @ K^T  (this thread: rows ty*4.., cols tx*4..)
        float s[4][4];
        #pragma unroll
        for (int i = 0; i < 4; i++)
            #pragma unroll
            for (int j = 0; j < 4; j++) s[i][j] = 0.0f;

        #pragma unroll 4
        for (int d = 0; d < 64; d++) {
            float a0 = Qt[d * 65 + ty * 4 + 0];
            float a1 = Qt[d * 65 + ty * 4 + 1];
            float a2 = Qt[d * 65 + ty * 4 + 2];
            float a3 = Qt[d * 65 + ty * 4 + 3];
            float b0 = Kt[d * 65 + tx * 4 + 0];
            float b1 = Kt[d * 65 + tx * 4 + 1];
            float b2 = Kt[d * 65 + tx * 4 + 2];
            float b3 = Kt[d * 65 + tx * 4 + 3];
            s[0][0] = fmaf(a0,b0,s[0][0]); s[0][1] = fmaf(a0,b1,s[0][1]);
            s[0][2] = fmaf(a0,b2,s[0][2]); s[0][3] = fmaf(a0,b3,s[0][3]);
            s[1][0] = fmaf(a1,b0,s[1][0]); s[1][1] = fmaf(a1,b1,s[1][1]);
            s[1][2] = fmaf(a1,b2,s[1][2]); s[1][3] = fmaf(a1,b3,s[1][3]);
            s[2][0] = fmaf(a2,b0,s[2][0]); s[2][1] = fmaf(a2,b1,s[2][1]);
            s[2][2] = fmaf(a2,b2,s[2][2]); s[2][3] = fmaf(a2,b3,s[2][3]);
            s[3][0] = fmaf(a3,b0,s[3][0]); s[3][1] = fmaf(a3,b1,s[3][1]);
            s[3][2] = fmaf(a3,b2,s[3][2]); s[3][3] = fmaf(a3,b3,s[3][3]);
        }

        // scale + causal mask (only the diagonal tile needs masking)
        const bool diag = (k0 == q0);
        #pragma unroll
        for (int i = 0; i < 4; i++)
            #pragma unroll
            for (int j = 0; j < 4; j++) {
                s[i][j] *= scale;
                if (diag && (tx * 4 + j) > (ty * 4 + i)) s[i][j] = -1e30f;
            }

        // online softmax update (row reductions across 16 lanes via shfl)
        #pragma unroll
        for (int i = 0; i < 4; i++) {
            float rmax = fmaxf(fmaxf(s[i][0], s[i][1]), fmaxf(s[i][2], s[i][3]));
            #pragma unroll
            for (int off = 1; off < 16; off <<= 1)
                rmax = fmaxf(rmax, __shfl_xor_sync(0xffffffffu, rmax, off));
            float mn = fmaxf(m[i], rmax);
            float sc = __expf(m[i] - mn);
            m[i] = mn;
            #pragma unroll
            for (int j = 0; j < 4; j++) o[i][j] *= sc;
            float rs = 0.0f;
            #pragma unroll
            for (int j = 0; j < 4; j++) {
                float p = __expf(s[i][j] - mn);
                s[i][j] = p;
                rs += p;
            }
            #pragma unroll
            for (int off = 1; off < 16; off <<= 1)
                rs += __shfl_xor_sync(0xffffffffu, rs, off);
            l[i] = l[i] * sc + rs;
        }

        // stage P to smem
        #pragma unroll
        for (int i = 0; i < 4; i++)
            #pragma unroll
            for (int j = 0; j < 4; j++)
                Ps[(ty * 4 + i) * 65 + tx * 4 + j] = s[i][j];
        __syncthreads();

        // O += P @ V
        #pragma unroll 4
        for (int k = 0; k < 64; k++) {
            float a0 = Ps[(ty * 4 + 0) * 65 + k];
            float a1 = Ps[(ty * 4 + 1) * 65 + k];
            float a2 = Ps[(ty * 4 + 2) * 65 + k];
            float a3 = Ps[(ty * 4 + 3) * 65 + k];
            float b0 = Vs[k * 64 + tx * 4 + 0];
            float b1 = Vs[k * 64 + tx * 4 + 1];
            float b2 = Vs[k * 64 + tx * 4 + 2];
            float b3 = Vs[k * 64 + tx * 4 + 3];
            o[0][0] = fmaf(a0,b0,o[0][0]); o[0][1] = fmaf(a0,b1,o[0][1]);
            o[0][2] = fmaf(a0,b2,o[0][2]); o[0][3] = fmaf(a0,b3,o[0][3]);
            o[1][0] = fmaf(a1,b0,o[1][0]); o[1][1] = fmaf(a1,b1,o[1][1]);
            o[1][2] = fmaf(a1,b2,o[1][2]); o[1][3] = fmaf(a1,b3,o[1][3]);
            o[2][0] = fmaf(a2,b0,o[2][0]); o[2][1] = fmaf(a2,b1,o[2][1]);
            o[2][2] = fmaf(a2,b2,o[2][2]); o[2][3] = fmaf(a2,b3,o[2][3]);
            o[3][0] = fmaf(a3,b0,o[3][0]); o[3][1] = fmaf(a3,b1,o[3][1]);
            o[3][2] = fmaf(a3,b2,o[3][2]); o[3][3] = fmaf(a3,b3,o[3][3]);
        }
    }

    // epilogue: normalize and write [B,S,H*HD]
    #pragma unroll
    for (int i = 0; i < 4; i++) {
        float inv = 1.0f / l[i];
        float* Op = O + (size_t)(b * SS + q0 + ty * 4 + i) * DD + h * HD + tx * 4;
        #pragma unroll
        for (int j = 0; j < 4; j++) Op[j] = o[i][j] * inv;
    }
}

// ---------------------------------------------------------------------------
// Launch
// ---------------------------------------------------------------------------
extern "C" void kernel_launch(void* const* d_in, const int* in_sizes, int n_in,
                              void* d_out, int out_size)
{
    (void)in_sizes; (void)n_in; (void)out_size;
    const float* x  = (const float*)d_in[0];
    const float* kv = (const float*)d_in[1];
    const float* Wq = (const float*)d_in[2];
    const float* bq = (const float*)d_in[3];
    const float* Wk = (const float*)d_in[4];
    const float* bk = (const float*)d_in[5];
    const float* Wv = (const float*)d_in[6];
    const float* bv = (const float*)d_in[7];
    const float* Wo = (const float*)d_in[8];
    const float* bo = (const float*)d_in[9];
    float* out = (float*)d_out;

    float *q, *k, *v, *ao;
    cudaGetSymbolAddress((void**)&q,  g_q);
    cudaGetSymbolAddress((void**)&k,  g_k);
    cudaGetSymbolAddress((void**)&v,  g_v);
    cudaGetSymbolAddress((void**)&ao, g_ao);

    cudaFuncSetAttribute(attn_kernel,
                         cudaFuncAttributeMaxDynamicSharedMemorySize,
                         ATTN_SMEM_BYTES);

    // Q/K/V projections
    gemm_bias_kernel<<<dim3(DD / 128,  MTOT / 128), 256>>>(x,  Wq, bq, q, MTOT, DD,  DD);
    gemm_bias_kernel<<<dim3(KVD / 128, MTOT / 128), 256>>>(kv, Wk, bk, k, MTOT, KVD, DD);
    gemm_bias_kernel<<<dim3(KVD / 128, MTOT / 128), 256>>>(kv, Wv, bv, v, MTOT, KVD, DD);

    // fused causal GQA attention
    attn_kernel<<<dim3(SS / 64, BB * HH), 256, ATTN_SMEM_BYTES>>>(q, k, v, ao);

    // output projection
    gemm_bias_kernel<<<dim3(DD / 128, MTOT / 128), 256>>>(ao, Wo, bo, out, MTOT, DD, DD);
}

// round 4
// speedup vs baseline: 3.4331x; 3.4331x over previous
#include <cuda_runtime.h>
#include <math.h>
#include <stdint.h>

// Problem constants (fixed shapes)
#define BB 2
#define SS 2048
#define DD 2048
#define HH 32
#define GG 8
#define HD 64
#define KVD 512        // G*HD
#define MTOT (BB*SS)   // 4096

// Scratch (static device globals; no allocation allowed)
__device__ float g_q [BB*SS*DD];
__device__ float g_k [BB*SS*KVD];
__device__ float g_v [BB*SS*KVD];
__device__ float g_ao[BB*SS*DD];

// ---------------------------------------------------------------------------
// helpers
// ---------------------------------------------------------------------------
__device__ __forceinline__ uint32_t f2tf(float x) {
    uint32_t r;
    asm("cvt.rna.tf32.f32 %0, %1;" : "=r"(r) : "f"(x));
    return r;
}
__device__ __forceinline__ uint32_t sptr(const void* p) {
    return (uint32_t)__cvta_generic_to_shared(p);
}
__device__ __forceinline__ void cpa16(uint32_t s, const void* g) {
    asm volatile("cp.async.cg.shared.global [%0], [%1], 16;" :: "r"(s), "l"(g));
}
#define CP_COMMIT() asm volatile("cp.async.commit_group;")
#define CP_WAIT(N)  asm volatile("cp.async.wait_group %0;" :: "n"(N))

__device__ __forceinline__ void mma_tf32(
    float& c0, float& c1, float& c2, float& c3,
    uint32_t a0, uint32_t a1, uint32_t a2, uint32_t a3,
    uint32_t b0, uint32_t b1)
{
    asm volatile(
        "mma.sync.aligned.m16n8k8.row.col.f32.tf32.tf32.f32 "
        "{%0,%1,%2,%3}, {%4,%5,%6,%7}, {%8,%9}, {%0,%1,%2,%3};"
        : "+f"(c0), "+f"(c1), "+f"(c2), "+f"(c3)
        : "r"(a0), "r"(a1), "r"(a2), "r"(a3), "r"(b0), "r"(b1));
}

// ---------------------------------------------------------------------------
// TF32 tensor-core GEMM + bias: C[M,N] = A[M,K] @ W[K,N] + bias[N]
// 128x128x32 tile, 256 threads (8 warps, each 64x32), cp.async double buffer.
// M%128==0, N%128==0, K%32==0 required (true for all calls).
// ---------------------------------------------------------------------------
#define AS_STRIDE 36    // 32 + 4 pad (floats)
#define BS_STRIDE 136   // 128 + 8 pad (floats)
#define GEMM_BUF_FLOATS (128*AS_STRIDE + 32*BS_STRIDE)
#define GEMM_SMEM_BYTES (2 * GEMM_BUF_FLOATS * 4)

__global__ void __launch_bounds__(256) gemm_tf32_kernel(
    const float* __restrict__ A, const float* __restrict__ W,
    const float* __restrict__ bias, float* __restrict__ C,
    int M, int N, int K)
{
    extern __shared__ float sm[];
    float* As0 = sm;
    float* Bs0 = As0 + 128*AS_STRIDE;
    float* As1 = Bs0 + 32*BS_STRIDE;
    float* Bs1 = As1 + 128*AS_STRIDE;

    const int tid  = threadIdx.x;
    const int lane = tid & 31;
    const int warp = tid >> 5;
    const int g    = lane >> 2;     // 0..7
    const int tig  = lane & 3;      // 0..3
    const int warpM = warp >> 2;    // 0..1
    const int warpN = warp & 3;     // 0..3
    const int row0 = blockIdx.y * 128;
    const int col0 = blockIdx.x * 128;

    float c[4][4][4];
    #pragma unroll
    for (int i = 0; i < 4; i++)
        #pragma unroll
        for (int j = 0; j < 4; j++)
            #pragma unroll
            for (int r = 0; r < 4; r++) c[i][j][r] = 0.0f;

    // precompute staging indices
    const int ar = tid >> 3;          // A row within tile (0..31 per it-chunk of 32? no: idx>>3)
    // (recomputed in loop from idx; kept simple below)

    const int nk = K >> 5;

    // prologue: tile 0 -> buffer 0
    {
        #pragma unroll
        for (int it = 0; it < 4; it++) {
            int idx = it * 256 + tid;
            int r = idx >> 3, kc = (idx & 7) << 2;
            cpa16(sptr(As0 + r * AS_STRIDE + kc),
                  A + (size_t)(row0 + r) * K + kc);
        }
        #pragma unroll
        for (int it = 0; it < 4; it++) {
            int idx = it * 256 + tid;
            int kr = idx >> 5, nc = (idx & 31) << 2;
            cpa16(sptr(Bs0 + kr * BS_STRIDE + nc),
                  W + (size_t)kr * N + col0 + nc);
        }
        CP_COMMIT();
    }

    for (int kt = 0; kt < nk; kt++) {
        const float* as = (kt & 1) ? As1 : As0;
        const float* bs = (kt & 1) ? Bs1 : Bs0;

        if (kt + 1 < nk) {
            float* asn = ((kt + 1) & 1) ? As1 : As0;
            float* bsn = ((kt + 1) & 1) ? Bs1 : Bs0;
            const int kbase = (kt + 1) << 5;
            #pragma unroll
            for (int it = 0; it < 4; it++) {
                int idx = it * 256 + tid;
                int r = idx >> 3, kc = (idx & 7) << 2;
                cpa16(sptr(asn + r * AS_STRIDE + kc),
                      A + (size_t)(row0 + r) * K + kbase + kc);
            }
            #pragma unroll
            for (int it = 0; it < 4; it++) {
                int idx = it * 256 + tid;
                int kr = idx >> 5, nc = (idx & 31) << 2;
                cpa16(sptr(bsn + kr * BS_STRIDE + nc),
                      W + (size_t)(kbase + kr) * N + col0 + nc);
            }
            CP_COMMIT();
            CP_WAIT(1);
        } else {
            CP_WAIT(0);
        }
        __syncthreads();

        #pragma unroll
        for (int ks = 0; ks < 4; ks++) {
            const int ko = ks * 8;
            uint32_t af[4][4];
            #pragma unroll
            for (int mt = 0; mt < 4; mt++) {
                const float* ap = as + (warpM * 64 + mt * 16 + g) * AS_STRIDE + ko + tig;
                af[mt][0] = f2tf(ap[0]);
                af[mt][1] = f2tf(ap[8 * AS_STRIDE]);
                af[mt][2] = f2tf(ap[4]);
                af[mt][3] = f2tf(ap[8 * AS_STRIDE + 4]);
            }
            uint32_t bf[4][2];
            #pragma unroll
            for (int nt = 0; nt < 4; nt++) {
                const float* bp = bs + (ko + tig) * BS_STRIDE + warpN * 32 + nt * 8 + g;
                bf[nt][0] = f2tf(bp[0]);
                bf[nt][1] = f2tf(bp[4 * BS_STRIDE]);
            }
            #pragma unroll
            for (int mt = 0; mt < 4; mt++)
                #pragma unroll
                for (int nt = 0; nt < 4; nt++)
                    mma_tf32(c[mt][nt][0], c[mt][nt][1], c[mt][nt][2], c[mt][nt][3],
                             af[mt][0], af[mt][1], af[mt][2], af[mt][3],
                             bf[nt][0], bf[nt][1]);
        }
        __syncthreads();
    }

    // epilogue: bias + store
    #pragma unroll
    for (int mt = 0; mt < 4; mt++) {
        const int r = row0 + warpM * 64 + mt * 16 + g;
        #pragma unroll
        for (int nt = 0; nt < 4; nt++) {
            const int cc = col0 + warpN * 32 + nt * 8 + 2 * tig;
            const float b0 = bias[cc], b1 = bias[cc + 1];
            *(float2*)(C + (size_t)r * N + cc) =
                make_float2(c[mt][nt][0] + b0, c[mt][nt][1] + b1);
            *(float2*)(C + (size_t)(r + 8) * N + cc) =
                make_float2(c[mt][nt][2] + b0, c[mt][nt][3] + b1);
        }
    }
}

// ---------------------------------------------------------------------------
// Fused causal GQA flash attention with TF32 MMA.
// Grid: (S/64, B*H). Block: 128 threads (4 warps, each 16 q-rows).
// ---------------------------------------------------------------------------
#define KS_STRIDE 68   // 64+4 : K b-frag banks = 4g+tig  (conflict-free)
#define VS_STRIDE 72   // 64+8 : V b-frag banks = 8tig+g  (conflict-free)
#define PS_STRIDE 68   // Q/P a-frag banks = 4g+tig       (conflict-free)
#define ATTN_SMEM_BYTES ((64*KS_STRIDE + 64*VS_STRIDE + 64*PS_STRIDE) * 4)

__global__ void __launch_bounds__(128) attn_tf32_kernel(
    const float* __restrict__ Q, const float* __restrict__ Kg,
    const float* __restrict__ Vg, float* __restrict__ O)
{
    extern __shared__ uint32_t smu[];
    uint32_t* Ks = smu;
    uint32_t* Vs = Ks + 64 * KS_STRIDE;
    uint32_t* Ps = Vs + 64 * VS_STRIDE;

    const int tid  = threadIdx.x;
    const int lane = tid & 31;
    const int warp = tid >> 5;
    const int g    = lane >> 2;
    const int tig  = lane & 3;
    const int wr   = warp * 16;

    const int qt = (int)gridDim.x - 1 - (int)blockIdx.x;  // heavy tiles first
    const int bh = blockIdx.y;
    const int b  = bh >> 5;
    const int h  = bh & 31;
    const int grp = h >> 2;
    const int q0 = qt * 64;

    const float* Qb = Q  + (size_t)(b * SS) * DD  + h * HD;
    const float* Kb = Kg + (size_t)(b * SS) * KVD + grp * HD;
    const float* Vb = Vg + (size_t)(b * SS) * KVD + grp * HD;

    // stage Q (tf32-converted) into Ps, then cache fragments in registers
    #pragma unroll
    for (int it = 0; it < 8; it++) {
        int idx = it * 128 + tid;
        int r = idx >> 4, dc = (idx & 15) << 2;
        float4 v = *(const float4*)(Qb + (size_t)(q0 + r) * DD + dc);
        uint4 u = make_uint4(f2tf(v.x), f2tf(v.y), f2tf(v.z), f2tf(v.w));
        *(uint4*)(Ps + r * PS_STRIDE + dc) = u;
    }
    __syncthreads();

    uint32_t qf[8][4];
    #pragma unroll
    for (int ks = 0; ks < 8; ks++) {
        const uint32_t* qp = Ps + (wr + g) * PS_STRIDE + ks * 8 + tig;
        qf[ks][0] = qp[0];
        qf[ks][1] = qp[8 * PS_STRIDE];
        qf[ks][2] = qp[4];
        qf[ks][3] = qp[8 * PS_STRIDE + 4];
    }

    float o[8][4];
    #pragma unroll
    for (int nt = 0; nt < 8; nt++)
        #pragma unroll
        for (int i = 0; i < 4; i++) o[nt][i] = 0.0f;
    float m0 = -1e30f, m1 = -1e30f, l0 = 0.0f, l1 = 0.0f;

    for (int t = 0; t <= qt; t++) {
        const int k0 = t * 64;
        __syncthreads();   // all warps done with previous Ks/Vs

        // stage K/V tiles (tf32-converted)
        #pragma unroll
        for (int it = 0; it < 8; it++) {
            int idx = it * 128 + tid;
            int r = idx >> 4, dc = (idx & 15) << 2;
            float4 kv = *(const float4*)(Kb + (size_t)(k0 + r) * KVD + dc);
            *(uint4*)(Ks + r * KS_STRIDE + dc) =
                make_uint4(f2tf(kv.x), f2tf(kv.y), f2tf(kv.z), f2tf(kv.w));
            float4 vv = *(const float4*)(Vb + (size_t)(k0 + r) * KVD + dc);
            *(uint4*)(Vs + r * VS_STRIDE + dc) =
                make_uint4(f2tf(vv.x), f2tf(vv.y), f2tf(vv.z), f2tf(vv.w));
        }
        __syncthreads();

        // S = Q @ K^T   (warp: 16 rows x 64 keys)
        float s[8][4];
        #pragma unroll
        for (int nt = 0; nt < 8; nt++)
            #pragma unroll
            for (int i = 0; i < 4; i++) s[nt][i] = 0.0f;

        #pragma unroll
        for (int ks = 0; ks < 8; ks++) {
            #pragma unroll
            for (int nt = 0; nt < 8; nt++) {
                const uint32_t* kp = Ks + (nt * 8 + g) * KS_STRIDE + ks * 8 + tig;
                mma_tf32(s[nt][0], s[nt][1], s[nt][2], s[nt][3],
                         qf[ks][0], qf[ks][1], qf[ks][2], qf[ks][3],
                         kp[0], kp[4]);
            }
        }

        // scale + causal mask (diag tile only)
        const bool diag = (t == qt);
        const int rowg = q0 + wr + g;
        #pragma unroll
        for (int nt = 0; nt < 8; nt++) {
            const int cbase = k0 + nt * 8 + 2 * tig;
            #pragma unroll
            for (int i = 0; i < 4; i++) {
                float v = s[nt][i] * 0.125f;
                if (diag) {
                    int col = cbase + (i & 1);
                    int row = rowg + ((i & 2) ? 8 : 0);
                    if (col > row) v = -1e30f;
                }
                s[nt][i] = v;
            }
        }

        // online softmax (rows g and g+8; stats shared across quad lanes)
        float r0 = -1e30f, r1 = -1e30f;
        #pragma unroll
        for (int nt = 0; nt < 8; nt++) {
            r0 = fmaxf(r0, fmaxf(s[nt][0], s[nt][1]));
            r1 = fmaxf(r1, fmaxf(s[nt][2], s[nt][3]));
        }
        r0 = fmaxf(r0, __shfl_xor_sync(0xffffffffu, r0, 1));
        r0 = fmaxf(r0, __shfl_xor_sync(0xffffffffu, r0, 2));
        r1 = fmaxf(r1, __shfl_xor_sync(0xffffffffu, r1, 1));
        r1 = fmaxf(r1, __shfl_xor_sync(0xffffffffu, r1, 2));

        const float mn0 = fmaxf(m0, r0), mn1 = fmaxf(m1, r1);
        const float e0 = __expf(m0 - mn0), e1 = __expf(m1 - mn1);
        m0 = mn0; m1 = mn1;

        float ls0 = 0.0f, ls1 = 0.0f;
        uint32_t* pbase = Ps + (wr + g) * PS_STRIDE;
        #pragma unroll
        for (int nt = 0; nt < 8; nt++) {
            o[nt][0] *= e0; o[nt][1] *= e0;
            o[nt][2] *= e1; o[nt][3] *= e1;
            float p0 = __expf(s[nt][0] - mn0), p1 = __expf(s[nt][1] - mn0);
            float p2 = __expf(s[nt][2] - mn1), p3 = __expf(s[nt][3] - mn1);
            ls0 += p0 + p1; ls1 += p2 + p3;
            uint32_t* pp = pbase + nt * 8 + 2 * tig;
            pp[0] = f2tf(p0); pp[1] = f2tf(p1);
            pp[8 * PS_STRIDE] = f2tf(p2); pp[8 * PS_STRIDE + 1] = f2tf(p3);
        }
        ls0 += __shfl_xor_sync(0xffffffffu, ls0, 1);
        ls0 += __shfl_xor_sync(0xffffffffu, ls0, 2);
        ls1 += __shfl_xor_sync(0xffffffffu, ls1, 1);
        ls1 += __shfl_xor_sync(0xffffffffu, ls1, 2);
        l0 = l0 * e0 + ls0;
        l1 = l1 * e1 + ls1;

        __syncwarp();   // P written to own-warp smem region, reread below

        // O += P @ V
        #pragma unroll
        for (int ks = 0; ks < 8; ks++) {
            const uint32_t* pp = Ps + (wr + g) * PS_STRIDE + ks * 8 + tig;
            const uint32_t a0 = pp[0];
            const uint32_t a1 = pp[8 * PS_STRIDE];
            const uint32_t a2 = pp[4];
            const uint32_t a3 = pp[8 * PS_STRIDE + 4];
            #pragma unroll
            for (int nt = 0; nt < 8; nt++) {
                const uint32_t* vp = Vs + (ks * 8 + tig) * VS_STRIDE + nt * 8 + g;
                mma_tf32(o[nt][0], o[nt][1], o[nt][2], o[nt][3],
                         a0, a1, a2, a3, vp[0], vp[4 * VS_STRIDE]);
            }
        }
    }

    // epilogue: normalize and store
    const float inv0 = 1.0f / l0, inv1 = 1.0f / l1;
    float* Ob = O + (size_t)(b * SS + q0 + wr + g) * DD + h * HD;
    #pragma unroll
    for (int nt = 0; nt < 8; nt++) {
        const int cc = nt * 8 + 2 * tig;
        *(float2*)(Ob + cc) = make_float2(o[nt][0] * inv0, o[nt][1] * inv0);
        *(float2*)(Ob + 8 * DD + cc) = make_float2(o[nt][2] * inv1, o[nt][3] * inv1);
    }
}

// ---------------------------------------------------------------------------
// Launch
// ---------------------------------------------------------------------------
extern "C" void kernel_launch(void* const* d_in, const int* in_sizes, int n_in,
                              void* d_out, int out_size)
{
    (void)in_sizes; (void)n_in; (void)out_size;
    const float* x  = (const float*)d_in[0];
    const float* kv = (const float*)d_in[1];
    const float* Wq = (const float*)d_in[2];
    const float* bq = (const float*)d_in[3];
    const float* Wk = (const float*)d_in[4];
    const float* bk = (const float*)d_in[5];
    const float* Wv = (const float*)d_in[6];
    const float* bv = (const float*)d_in[7];
    const float* Wo = (const float*)d_in[8];
    const float* bo = (const float*)d_in[9];
    float* out = (float*)d_out;

    float *q, *k, *v, *ao;
    cudaGetSymbolAddress((void**)&q,  g_q);
    cudaGetSymbolAddress((void**)&k,  g_k);
    cudaGetSymbolAddress((void**)&v,  g_v);
    cudaGetSymbolAddress((void**)&ao, g_ao);

    cudaFuncSetAttribute(gemm_tf32_kernel,
                         cudaFuncAttributeMaxDynamicSharedMemorySize,
                         GEMM_SMEM_BYTES);
    cudaFuncSetAttribute(attn_tf32_kernel,
                         cudaFuncAttributeMaxDynamicSharedMemorySize,
                         ATTN_SMEM_BYTES);

    // projections
    gemm_tf32_kernel<<<dim3(DD / 128,  MTOT / 128), 256, GEMM_SMEM_BYTES>>>(
        x,  Wq, bq, q, MTOT, DD,  DD);
    gemm_tf32_kernel<<<dim3(KVD / 128, MTOT / 128), 256, GEMM_SMEM_BYTES>>>(
        kv, Wk, bk, k, MTOT, KVD, DD);
    gemm_tf32_kernel<<<dim3(KVD / 128, MTOT / 128), 256, GEMM_SMEM_BYTES>>>(
        kv, Wv, bv, v, MTOT, KVD, DD);

    // fused causal GQA attention
    attn_tf32_kernel<<<dim3(SS / 64, BB * HH), 128, ATTN_SMEM_BYTES>>>(q, k, v, ao);

    // output projection
    gemm_tf32_kernel<<<dim3(DD / 128, MTOT / 128), 256, GEMM_SMEM_BYTES>>>(
        ao, Wo, bo, out, MTOT, DD, DD);
}

// round 5
// speedup vs baseline: 3.5143x; 1.0237x over previous
#include <cuda_runtime.h>
#include <math.h>
#include <stdint.h>

// Problem constants (fixed shapes)
#define BB 2
#define SS 2048
#define DD 2048
#define HH 32
#define GG 8
#define HD 64
#define KVD 512        // G*HD
#define MTOT (BB*SS)   // 4096

// Scratch (static device globals; no allocation allowed)
__device__ float g_q [BB*SS*DD];
__device__ float g_k [BB*SS*KVD];
__device__ float g_v [BB*SS*KVD];
__device__ float g_ao[BB*SS*DD];

// ---------------------------------------------------------------------------
// helpers
// ---------------------------------------------------------------------------
__device__ __forceinline__ uint32_t f2tf(float x) {
    uint32_t r;
    asm("cvt.rna.tf32.f32 %0, %1;" : "=r"(r) : "f"(x));
    return r;
}
__device__ __forceinline__ uint32_t sptr(const void* p) {
    return (uint32_t)__cvta_generic_to_shared(p);
}
__device__ __forceinline__ void cpa16(uint32_t s, const void* g) {
    asm volatile("cp.async.cg.shared.global [%0], [%1], 16;" :: "r"(s), "l"(g));
}
#define CP_COMMIT() asm volatile("cp.async.commit_group;")
#define CP_WAIT(N)  asm volatile("cp.async.wait_group %0;" :: "n"(N))

__device__ __forceinline__ void mma_tf32(
    float& c0, float& c1, float& c2, float& c3,
    uint32_t a0, uint32_t a1, uint32_t a2, uint32_t a3,
    uint32_t b0, uint32_t b1)
{
    asm volatile(
        "mma.sync.aligned.m16n8k8.row.col.f32.tf32.tf32.f32 "
        "{%0,%1,%2,%3}, {%4,%5,%6,%7}, {%8,%9}, {%0,%1,%2,%3};"
        : "+f"(c0), "+f"(c1), "+f"(c2), "+f"(c3)
        : "r"(a0), "r"(a1), "r"(a2), "r"(a3), "r"(b0), "r"(b1));
}
__device__ __forceinline__ void mma_tf32v(float c[4], const uint32_t a[4],
                                          uint32_t b0, uint32_t b1)
{
    mma_tf32(c[0], c[1], c[2], c[3], a[0], a[1], a[2], a[3], b0, b1);
}

// ---------------------------------------------------------------------------
// TF32 tensor-core GEMM + bias body: C[M,N] = A[M,K] @ W[K,N] + bias[N]
// 128x128x32 tile, 256 threads (8 warps, each 64x32), cp.async double buffer.
// ---------------------------------------------------------------------------
#define AS_STRIDE 36
#define BS_STRIDE 136
#define GEMM_BUF_FLOATS (128*AS_STRIDE + 32*BS_STRIDE)
#define GEMM_SMEM_BYTES (2 * GEMM_BUF_FLOATS * 4)

__device__ __forceinline__ void gemm_body(
    const float* __restrict__ A, const float* __restrict__ W,
    const float* __restrict__ bias, float* __restrict__ C,
    int N, int K, int row0, int col0, float* sm)
{
    float* As0 = sm;
    float* Bs0 = As0 + 128*AS_STRIDE;
    float* As1 = Bs0 + 32*BS_STRIDE;
    float* Bs1 = As1 + 128*AS_STRIDE;

    const int tid  = threadIdx.x;
    const int lane = tid & 31;
    const int warp = tid >> 5;
    const int g    = lane >> 2;
    const int tig  = lane & 3;
    const int warpM = warp >> 2;
    const int warpN = warp & 3;

    float c[4][4][4];
    #pragma unroll
    for (int i = 0; i < 4; i++)
        #pragma unroll
        for (int j = 0; j < 4; j++)
            #pragma unroll
            for (int r = 0; r < 4; r++) c[i][j][r] = 0.0f;

    const int nk = K >> 5;

    // prologue: tile 0 -> buffer 0
    #pragma unroll
    for (int it = 0; it < 4; it++) {
        int idx = it * 256 + tid;
        int r = idx >> 3, kc = (idx & 7) << 2;
        cpa16(sptr(As0 + r * AS_STRIDE + kc),
              A + (size_t)(row0 + r) * K + kc);
    }
    #pragma unroll
    for (int it = 0; it < 4; it++) {
        int idx = it * 256 + tid;
        int kr = idx >> 5, nc = (idx & 31) << 2;
        cpa16(sptr(Bs0 + kr * BS_STRIDE + nc),
              W + (size_t)kr * N + col0 + nc);
    }
    CP_COMMIT();

    for (int kt = 0; kt < nk; kt++) {
        const float* as = (kt & 1) ? As1 : As0;
        const float* bs = (kt & 1) ? Bs1 : Bs0;

        if (kt + 1 < nk) {
            float* asn = ((kt + 1) & 1) ? As1 : As0;
            float* bsn = ((kt + 1) & 1) ? Bs1 : Bs0;
            const int kbase = (kt + 1) << 5;
            #pragma unroll
            for (int it = 0; it < 4; it++) {
                int idx = it * 256 + tid;
                int r = idx >> 3, kc = (idx & 7) << 2;
                cpa16(sptr(asn + r * AS_STRIDE + kc),
                      A + (size_t)(row0 + r) * K + kbase + kc);
            }
            #pragma unroll
            for (int it = 0; it < 4; it++) {
                int idx = it * 256 + tid;
                int kr = idx >> 5, nc = (idx & 31) << 2;
                cpa16(sptr(bsn + kr * BS_STRIDE + nc),
                      W + (size_t)(kbase + kr) * N + col0 + nc);
            }
            CP_COMMIT();
            CP_WAIT(1);
        } else {
            CP_WAIT(0);
        }
        __syncthreads();

        #pragma unroll
        for (int ks = 0; ks < 4; ks++) {
            const int ko = ks * 8;
            uint32_t af[4][4];
            #pragma unroll
            for (int mt = 0; mt < 4; mt++) {
                const float* ap = as + (warpM * 64 + mt * 16 + g) * AS_STRIDE + ko + tig;
                af[mt][0] = f2tf(ap[0]);
                af[mt][1] = f2tf(ap[8 * AS_STRIDE]);
                af[mt][2] = f2tf(ap[4]);
                af[mt][3] = f2tf(ap[8 * AS_STRIDE + 4]);
            }
            uint32_t bf[4][2];
            #pragma unroll
            for (int nt = 0; nt < 4; nt++) {
                const float* bp = bs + (ko + tig) * BS_STRIDE + warpN * 32 + nt * 8 + g;
                bf[nt][0] = f2tf(bp[0]);
                bf[nt][1] = f2tf(bp[4 * BS_STRIDE]);
            }
            #pragma unroll
            for (int mt = 0; mt < 4; mt++)
                #pragma unroll
                for (int nt = 0; nt < 4; nt++)
                    mma_tf32(c[mt][nt][0], c[mt][nt][1], c[mt][nt][2], c[mt][nt][3],
                             af[mt][0], af[mt][1], af[mt][2], af[mt][3],
                             bf[nt][0], bf[nt][1]);
        }
        __syncthreads();
    }

    #pragma unroll
    for (int mt = 0; mt < 4; mt++) {
        const int r = row0 + warpM * 64 + mt * 16 + g;
        #pragma unroll
        for (int nt = 0; nt < 4; nt++) {
            const int cc = col0 + warpN * 32 + nt * 8 + 2 * tig;
            const float b0 = bias[cc], b1 = bias[cc + 1];
            *(float2*)(C + (size_t)r * N + cc) =
                make_float2(c[mt][nt][0] + b0, c[mt][nt][1] + b1);
            *(float2*)(C + (size_t)(r + 8) * N + cc) =
                make_float2(c[mt][nt][2] + b0, c[mt][nt][3] + b1);
        }
    }
}

__global__ void __launch_bounds__(256) gemm_tf32_kernel(
    const float* __restrict__ A, const float* __restrict__ W,
    const float* __restrict__ bias, float* __restrict__ C,
    int N, int K)
{
    extern __shared__ float sm[];
    gemm_body(A, W, bias, C, N, K, blockIdx.y * 128, blockIdx.x * 128, sm);
}

// Fused K+V projection: grid.x = 8 (4 tiles K, 4 tiles V), N = 512 each
__global__ void __launch_bounds__(256) gemm_tf32_kv_kernel(
    const float* __restrict__ A,
    const float* __restrict__ Wk, const float* __restrict__ bk, float* __restrict__ Ck,
    const float* __restrict__ Wv, const float* __restrict__ bv, float* __restrict__ Cv,
    int K)
{
    extern __shared__ float sm[];
    const int bx = blockIdx.x;
    if (bx < 4)
        gemm_body(A, Wk, bk, Ck, KVD, K, blockIdx.y * 128, bx * 128, sm);
    else
        gemm_body(A, Wv, bv, Cv, KVD, K, blockIdx.y * 128, (bx - 4) * 128, sm);
}

// ---------------------------------------------------------------------------
// Fused causal GQA flash attention, TF32 MMA.
// Grid: (8 q-block pairs, B*H). Block: 128 threads (4 warps).
// Each block handles q-blocks (p, 15-p) of 128 rows each -> 36 k-tiles total.
// Each warp owns 32 q-rows (2 row-groups of 16), sharing K/V b-fragments.
// K and Q stored in paired (k, k+4) layout -> single LDS.64 fragment loads.
// ---------------------------------------------------------------------------
#define KST 72    // 64 words (32 uint2 pairs) + 8 pad ; stride%32==8 -> CF
#define VST 72    // 64 words + 8 pad ; LDS.32 banks 8*tig+g -> CF
#define QST 72    // paired like K
#define PST 68    // unpaired ; LDS.32 banks 4*g+tig -> CF
#define ATTN_SMEM_WORDS (64*KST + 64*VST + 128*QST + 128*PST)
#define ATTN_SMEM_BYTES (ATTN_SMEM_WORDS * 4)

__global__ void __launch_bounds__(128) attn_tf32_kernel(
    const float* __restrict__ Q, const float* __restrict__ Kg,
    const float* __restrict__ Vg, float* __restrict__ O)
{
    extern __shared__ uint32_t smu[];
    uint32_t* Ks = smu;
    uint32_t* Vs = Ks + 64 * KST;
    uint32_t* Qs = Vs + 64 * VST;
    uint32_t* Ps = Qs + 128 * QST;

    const int tid  = threadIdx.x;
    const int lane = tid & 31;
    const int warp = tid >> 5;
    const int g    = lane >> 2;
    const int tig  = lane & 3;
    const int wr   = warp * 16;

    const int pr = blockIdx.x;          // pair index 0..7
    const int bh = blockIdx.y;
    const int b  = bh >> 5;
    const int h  = bh & 31;
    const int grp = h >> 2;

    const float* Qb = Q  + (size_t)(b * SS) * DD  + h * HD;
    const float* Kb = Kg + (size_t)(b * SS) * KVD + grp * HD;
    const float* Vb = Vg + (size_t)(b * SS) * KVD + grp * HD;

    for (int halfp = 0; halfp < 2; halfp++) {
        const int Qi = halfp ? (15 - pr) : pr;
        const int q0 = Qi * 128;

        __syncthreads();   // previous q-block done reading Qs

        // ---- stage Q (128 rows x 64 dims), tf32 + (k,k+4) pairing ----
        #pragma unroll
        for (int it = 0; it < 8; it++) {
            int idx = it * 128 + tid;
            int r = idx >> 3, c = idx & 7;
            const float* gp = Qb + (size_t)(q0 + r) * DD + c * 8;
            float4 v0 = *(const float4*)gp;
            float4 v1 = *(const float4*)(gp + 4);
            uint32_t* qp = Qs + r * QST + c * 8;
            *(uint4*)qp       = make_uint4(f2tf(v0.x), f2tf(v1.x), f2tf(v0.y), f2tf(v1.y));
            *(uint4*)(qp + 4) = make_uint4(f2tf(v0.z), f2tf(v1.z), f2tf(v0.w), f2tf(v1.w));
        }

        float o[2][8][4];
        float m[2][2], l[2][2];
        #pragma unroll
        for (int rg = 0; rg < 2; rg++) {
            m[rg][0] = -1e30f; m[rg][1] = -1e30f;
            l[rg][0] = 0.0f;   l[rg][1] = 0.0f;
            #pragma unroll
            for (int nt = 0; nt < 8; nt++)
                #pragma unroll
                for (int i = 0; i < 4; i++) o[rg][nt][i] = 0.0f;
        }

        const int tmax = 2 * Qi + 1;
        for (int t = 0; t <= tmax; t++) {
            const int k0 = t * 64;
            __syncthreads();   // prev iteration done reading Ks/Vs (+Q visible)

            // ---- stage K (paired) ----
            #pragma unroll
            for (int it = 0; it < 4; it++) {
                int idx = it * 128 + tid;
                int r = idx >> 3, c = idx & 7;
                const float* gp = Kb + (size_t)(k0 + r) * KVD + c * 8;
                float4 v0 = *(const float4*)gp;
                float4 v1 = *(const float4*)(gp + 4);
                uint32_t* kp = Ks + r * KST + c * 8;
                *(uint4*)kp       = make_uint4(f2tf(v0.x), f2tf(v1.x), f2tf(v0.y), f2tf(v1.y));
                *(uint4*)(kp + 4) = make_uint4(f2tf(v0.z), f2tf(v1.z), f2tf(v0.w), f2tf(v1.w));
            }
            // ---- stage V (unpaired) ----
            #pragma unroll
            for (int it = 0; it < 8; it++) {
                int idx = it * 128 + tid;
                int r = idx >> 4, dc = (idx & 15) << 2;
                float4 v = *(const float4*)(Vb + (size_t)(k0 + r) * KVD + dc);
                *(uint4*)(Vs + r * VST + dc) =
                    make_uint4(f2tf(v.x), f2tf(v.y), f2tf(v.z), f2tf(v.w));
            }
            __syncthreads();

            // ---- S = Q @ K^T  (both row-groups share each K b-fragment) ----
            float s[2][8][4];
            #pragma unroll
            for (int rg = 0; rg < 2; rg++)
                #pragma unroll
                for (int nt = 0; nt < 8; nt++)
                    #pragma unroll
                    for (int i = 0; i < 4; i++) s[rg][nt][i] = 0.0f;

            #pragma unroll
            for (int ks = 0; ks < 8; ks++) {
                uint32_t af[2][4];
                #pragma unroll
                for (int rg = 0; rg < 2; rg++) {
                    const uint32_t* qp = Qs + (rg * 64 + wr + g) * QST + ks * 8 + 2 * tig;
                    uint2 u0 = *(const uint2*)qp;
                    uint2 u8 = *(const uint2*)(qp + 8 * QST);
                    af[rg][0] = u0.x; af[rg][1] = u8.x;
                    af[rg][2] = u0.y; af[rg][3] = u8.y;
                }
                #pragma unroll
                for (int nt = 0; nt < 8; nt++) {
                    uint2 kb = *(const uint2*)(Ks + (nt * 8 + g) * KST + ks * 8 + 2 * tig);
                    mma_tf32v(s[0][nt], af[0], kb.x, kb.y);
                    mma_tf32v(s[1][nt], af[1], kb.x, kb.y);
                }
            }

            // ---- scale + causal mask + online softmax per row-group ----
            #pragma unroll
            for (int rg = 0; rg < 2; rg++) {
                const bool needmask = (t >= 2 * Qi + rg);
                const int rowg = q0 + rg * 64 + wr + g;
                #pragma unroll
                for (int nt = 0; nt < 8; nt++) {
                    const int cbase = k0 + nt * 8 + 2 * tig;
                    #pragma unroll
                    for (int i = 0; i < 4; i++) {
                        float v = s[rg][nt][i] * 0.125f;
                        if (needmask) {
                            int col = cbase + (i & 1);
                            int row = rowg + ((i & 2) ? 8 : 0);
                            if (col > row) v = -1e30f;
                        }
                        s[rg][nt][i] = v;
                    }
                }

                float r0 = -1e30f, r1 = -1e30f;
                #pragma unroll
                for (int nt = 0; nt < 8; nt++) {
                    r0 = fmaxf(r0, fmaxf(s[rg][nt][0], s[rg][nt][1]));
                    r1 = fmaxf(r1, fmaxf(s[rg][nt][2], s[rg][nt][3]));
                }
                r0 = fmaxf(r0, __shfl_xor_sync(0xffffffffu, r0, 1));
                r0 = fmaxf(r0, __shfl_xor_sync(0xffffffffu, r0, 2));
                r1 = fmaxf(r1, __shfl_xor_sync(0xffffffffu, r1, 1));
                r1 = fmaxf(r1, __shfl_xor_sync(0xffffffffu, r1, 2));

                const float mn0 = fmaxf(m[rg][0], r0), mn1 = fmaxf(m[rg][1], r1);
                const float e0 = __expf(m[rg][0] - mn0), e1 = __expf(m[rg][1] - mn1);
                m[rg][0] = mn0; m[rg][1] = mn1;

                float ls0 = 0.0f, ls1 = 0.0f;
                uint32_t* pbase = Ps + (rg * 64 + wr + g) * PST;
                #pragma unroll
                for (int nt = 0; nt < 8; nt++) {
                    o[rg][nt][0] *= e0; o[rg][nt][1] *= e0;
                    o[rg][nt][2] *= e1; o[rg][nt][3] *= e1;
                    float p0 = __expf(s[rg][nt][0] - mn0);
                    float p1 = __expf(s[rg][nt][1] - mn0);
                    float p2 = __expf(s[rg][nt][2] - mn1);
                    float p3 = __expf(s[rg][nt][3] - mn1);
                    ls0 += p0 + p1; ls1 += p2 + p3;
                    uint32_t* pp = pbase + nt * 8 + 2 * tig;
                    *(uint2*)pp             = make_uint2(f2tf(p0), f2tf(p1));
                    *(uint2*)(pp + 8 * PST) = make_uint2(f2tf(p2), f2tf(p3));
                }
                ls0 += __shfl_xor_sync(0xffffffffu, ls0, 1);
                ls0 += __shfl_xor_sync(0xffffffffu, ls0, 2);
                ls1 += __shfl_xor_sync(0xffffffffu, ls1, 1);
                ls1 += __shfl_xor_sync(0xffffffffu, ls1, 2);
                l[rg][0] = l[rg][0] * e0 + ls0;
                l[rg][1] = l[rg][1] * e1 + ls1;
            }

            __syncwarp();   // P written to own-warp rows, reread below

            // ---- O += P @ V  (both row-groups share each V b-fragment) ----
            #pragma unroll
            for (int ks = 0; ks < 8; ks++) {
                uint32_t pa[2][4];
                #pragma unroll
                for (int rg = 0; rg < 2; rg++) {
                    const uint32_t* pp = Ps + (rg * 64 + wr + g) * PST + ks * 8 + tig;
                    pa[rg][0] = pp[0];
                    pa[rg][1] = pp[8 * PST];
                    pa[rg][2] = pp[4];
                    pa[rg][3] = pp[8 * PST + 4];
                }
                #pragma unroll
                for (int nt = 0; nt < 8; nt++) {
                    const uint32_t* vp = Vs + (ks * 8 + tig) * VST + nt * 8 + g;
                    const uint32_t b0 = vp[0];
                    const uint32_t b1 = vp[4 * VST];
                    mma_tf32v(o[0][nt], pa[0], b0, b1);
                    mma_tf32v(o[1][nt], pa[1], b0, b1);
                }
            }
        }

        // ---- epilogue ----
        #pragma unroll
        for (int rg = 0; rg < 2; rg++) {
            const float inv0 = 1.0f / l[rg][0], inv1 = 1.0f / l[rg][1];
            float* Ob = O + (size_t)(b * SS + q0 + rg * 64 + wr + g) * DD + h * HD;
            #pragma unroll
            for (int nt = 0; nt < 8; nt++) {
                const int cc = nt * 8 + 2 * tig;
                *(float2*)(Ob + cc) =
                    make_float2(o[rg][nt][0] * inv0, o[rg][nt][1] * inv0);
                *(float2*)(Ob + 8 * DD + cc) =
                    make_float2(o[rg][nt][2] * inv1, o[rg][nt][3] * inv1);
            }
        }
    }
}

// ---------------------------------------------------------------------------
// Launch
// ---------------------------------------------------------------------------
extern "C" void kernel_launch(void* const* d_in, const int* in_sizes, int n_in,
                              void* d_out, int out_size)
{
    (void)in_sizes; (void)n_in; (void)out_size;
    const float* x  = (const float*)d_in[0];
    const float* kv = (const float*)d_in[1];
    const float* Wq = (const float*)d_in[2];
    const float* bq = (const float*)d_in[3];
    const float* Wk = (const float*)d_in[4];
    const float* bk = (const float*)d_in[5];
    const float* Wv = (const float*)d_in[6];
    const float* bv = (const float*)d_in[7];
    const float* Wo = (const float*)d_in[8];
    const float* bo = (const float*)d_in[9];
    float* out = (float*)d_out;

    float *q, *k, *v, *ao;
    cudaGetSymbolAddress((void**)&q,  g_q);
    cudaGetSymbolAddress((void**)&k,  g_k);
    cudaGetSymbolAddress((void**)&v,  g_v);
    cudaGetSymbolAddress((void**)&ao, g_ao);

    cudaFuncSetAttribute(gemm_tf32_kernel,
                         cudaFuncAttributeMaxDynamicSharedMemorySize,
                         GEMM_SMEM_BYTES);
    cudaFuncSetAttribute(gemm_tf32_kv_kernel,
                         cudaFuncAttributeMaxDynamicSharedMemorySize,
                         GEMM_SMEM_BYTES);
    cudaFuncSetAttribute(attn_tf32_kernel,
                         cudaFuncAttributeMaxDynamicSharedMemorySize,
                         ATTN_SMEM_BYTES);

    // Q projection
    gemm_tf32_kernel<<<dim3(DD / 128, MTOT / 128), 256, GEMM_SMEM_BYTES>>>(
        x, Wq, bq, q, DD, DD);
    // fused K+V projections
    gemm_tf32_kv_kernel<<<dim3(8, MTOT / 128), 256, GEMM_SMEM_BYTES>>>(
        kv, Wk, bk, k, Wv, bv, v, DD);

    // fused causal GQA attention (8 balanced q-block pairs x 64 bh)
    attn_tf32_kernel<<<dim3(8, BB * HH), 128, ATTN_SMEM_BYTES>>>(q, k, v, ao);

    // output projection
    gemm_tf32_kernel<<<dim3(DD / 128, MTOT / 128), 256, GEMM_SMEM_BYTES>>>(
        ao, Wo, bo, out, DD, DD);
}

// round 6
// speedup vs baseline: 3.6209x; 1.0303x over previous
#include <cuda_runtime.h>
#include <math.h>
#include <stdint.h>

// Problem constants (fixed shapes)
#define BB 2
#define SS 2048
#define DD 2048
#define HH 32
#define GG 8
#define HD 64
#define KVD 512        // G*HD
#define MTOT (BB*SS)   // 4096

// Scratch (static device globals; no allocation allowed)
__device__ float    g_q  [MTOT*DD];
__device__ float    g_k  [MTOT*KVD];
__device__ float    g_v  [MTOT*KVD];
__device__ float    g_ao [MTOT*DD];   // attention out: tf32 bits, (k,k+4)-paired rows
__device__ uint32_t g_xp [MTOT*DD];   // x,  tf32 + paired rows
__device__ uint32_t g_kvp[MTOT*DD];   // kv, tf32 + paired rows
__device__ uint32_t g_wqp[DD*DD];     // weights: tf32, pair-row interleaved [K/2][N][2]
__device__ uint32_t g_wkp[DD*KVD];
__device__ uint32_t g_wvp[DD*KVD];
__device__ uint32_t g_wop[DD*DD];

// ---------------------------------------------------------------------------
// helpers
// ---------------------------------------------------------------------------
__device__ __forceinline__ uint32_t f2tf(float x) {
    uint32_t r;
    asm("cvt.rna.tf32.f32 %0, %1;" : "=r"(r) : "f"(x));
    return r;
}
__device__ __forceinline__ uint32_t sptr(const void* p) {
    return (uint32_t)__cvta_generic_to_shared(p);
}
__device__ __forceinline__ void cpa16(uint32_t s, const void* g) {
    asm volatile("cp.async.cg.shared.global [%0], [%1], 16;" :: "r"(s), "l"(g));
}
#define CP_COMMIT() asm volatile("cp.async.commit_group;")
#define CP_WAIT(N)  asm volatile("cp.async.wait_group %0;" :: "n"(N))

__device__ __forceinline__ void mma_tf32(
    float& c0, float& c1, float& c2, float& c3,
    uint32_t a0, uint32_t a1, uint32_t a2, uint32_t a3,
    uint32_t b0, uint32_t b1)
{
    asm volatile(
        "mma.sync.aligned.m16n8k8.row.col.f32.tf32.tf32.f32 "
        "{%0,%1,%2,%3}, {%4,%5,%6,%7}, {%8,%9}, {%0,%1,%2,%3};"
        : "+f"(c0), "+f"(c1), "+f"(c2), "+f"(c3)
        : "r"(a0), "r"(a1), "r"(a2), "r"(a3), "r"(b0), "r"(b1));
}
__device__ __forceinline__ void mma_tf32v(float c[4], const uint32_t a[4],
                                          uint32_t b0, uint32_t b1)
{
    mma_tf32(c[0], c[1], c[2], c[3], a[0], a[1], a[2], a[3], b0, b1);
}

// ---------------------------------------------------------------------------
// Pre-pass kernels: tf32-convert + pair once, removing all cvt from GEMMs.
// Row pairing (A side): within each 8-float group of a row, word order
//   (k0,k4,k1,k5,k2,k6,k3,k7)  -> a-fragments become LDS.64.
// Weight pairing (B side): k-rows interleaved in (k,k+4) pairs:
//   Wp[p][n][c], p=(k/8)*4+(k%4), c=(k/4)&1 -> b-fragments become LDS.64.
// ---------------------------------------------------------------------------
__global__ void __launch_bounds__(256) pair_rows_kernel(
    const float4* __restrict__ in, uint4* __restrict__ out)
{
    const int idx = blockIdx.x * 256 + threadIdx.x;   // one 8-float group
    const float4 v0 = in[idx * 2];
    const float4 v1 = in[idx * 2 + 1];
    out[idx * 2]     = make_uint4(f2tf(v0.x), f2tf(v1.x), f2tf(v0.y), f2tf(v1.y));
    out[idx * 2 + 1] = make_uint4(f2tf(v0.z), f2tf(v1.z), f2tf(v0.w), f2tf(v1.w));
}

__global__ void __launch_bounds__(256) pair_weights_kernel(
    const float* __restrict__ W, uint32_t* __restrict__ Wp, int N)
{
    const int idx = blockIdx.x * 256 + threadIdx.x;
    const int ncq = N >> 2;
    const int p   = idx / ncq;          // pair index 0..K/2-1  (K=2048)
    const int nc  = idx - p * ncq;
    const int klo = (p >> 2) * 8 + (p & 3);
    const float4 lo = *(const float4*)(W + (size_t)klo * N + nc * 4);
    const float4 hi = *(const float4*)(W + (size_t)(klo + 4) * N + nc * 4);
    uint4* op = (uint4*)(Wp + (size_t)p * (2 * N) + nc * 8);
    op[0] = make_uint4(f2tf(lo.x), f2tf(hi.x), f2tf(lo.y), f2tf(hi.y));
    op[1] = make_uint4(f2tf(lo.z), f2tf(hi.z), f2tf(lo.w), f2tf(hi.w));
}

// ---------------------------------------------------------------------------
// TF32 GEMM + bias on pre-converted/pre-paired operands.
// C[M,N] = A[M,K] @ W[K,N] + bias[N].  128x128x32 tile, 256 threads,
// cp.async double buffer, zero cvt, all fragment loads LDS.64.
// ---------------------------------------------------------------------------
#define ASP 40     // A smem row stride (32 + 8 pad); a-frag banks 8g+2tig (CF)
#define BSP 264    // B smem pair-row stride (256 + 8); b-frag banks 8tig+2g (CF)
#define GEMM_BUF_WORDS (128*ASP + 16*BSP)
#define GEMM_SMEM_BYTES (2 * GEMM_BUF_WORDS * 4)

__device__ __forceinline__ void gemm_body(
    const uint32_t* __restrict__ Ap, const uint32_t* __restrict__ Wp,
    const float* __restrict__ bias, float* __restrict__ C,
    int N, int K, int row0, int col0, uint32_t* sm)
{
    uint32_t* As0 = sm;
    uint32_t* Bs0 = As0 + 128 * ASP;
    uint32_t* As1 = Bs0 + 16 * BSP;
    uint32_t* Bs1 = As1 + 128 * ASP;

    const int tid  = threadIdx.x;
    const int lane = tid & 31;
    const int warp = tid >> 5;
    const int g    = lane >> 2;
    const int tig  = lane & 3;
    const int warpM = warp >> 2;
    const int warpN = warp & 3;

    float c[4][4][4];
    #pragma unroll
    for (int i = 0; i < 4; i++)
        #pragma unroll
        for (int j = 0; j < 4; j++)
            #pragma unroll
            for (int r = 0; r < 4; r++) c[i][j][r] = 0.0f;

    const int nk = K >> 5;
    const size_t wrow = (size_t)(2 * N);

    // prologue: tile 0 -> buffer 0
    #pragma unroll
    for (int it = 0; it < 4; it++) {
        int idx = it * 256 + tid;
        int r = idx >> 3, w = (idx & 7) << 2;
        cpa16(sptr(As0 + r * ASP + w), Ap + (size_t)(row0 + r) * K + w);
    }
    #pragma unroll
    for (int it = 0; it < 4; it++) {
        int idx = it * 256 + tid;
        int pr = idx >> 6, w = (idx & 63) << 2;
        cpa16(sptr(Bs0 + pr * BSP + w), Wp + (size_t)pr * wrow + col0 * 2 + w);
    }
    CP_COMMIT();

    for (int kt = 0; kt < nk; kt++) {
        const uint32_t* as = (kt & 1) ? As1 : As0;
        const uint32_t* bs = (kt & 1) ? Bs1 : Bs0;

        if (kt + 1 < nk) {
            uint32_t* asn = ((kt + 1) & 1) ? As1 : As0;
            uint32_t* bsn = ((kt + 1) & 1) ? Bs1 : Bs0;
            const int kbase = (kt + 1) << 5;
            const int prg0  = (kt + 1) << 4;
            #pragma unroll
            for (int it = 0; it < 4; it++) {
                int idx = it * 256 + tid;
                int r = idx >> 3, w = (idx & 7) << 2;
                cpa16(sptr(asn + r * ASP + w),
                      Ap + (size_t)(row0 + r) * K + kbase + w);
            }
            #pragma unroll
            for (int it = 0; it < 4; it++) {
                int idx = it * 256 + tid;
                int pr = idx >> 6, w = (idx & 63) << 2;
                cpa16(sptr(bsn + pr * BSP + w),
                      Wp + (size_t)(prg0 + pr) * wrow + col0 * 2 + w);
            }
            CP_COMMIT();
            CP_WAIT(1);
        } else {
            CP_WAIT(0);
        }
        __syncthreads();

        #pragma unroll
        for (int ks = 0; ks < 4; ks++) {
            uint32_t af[4][4];
            #pragma unroll
            for (int mt = 0; mt < 4; mt++) {
                const uint32_t* ap = as + (warpM * 64 + mt * 16 + g) * ASP
                                        + ks * 8 + 2 * tig;
                uint2 u0 = *(const uint2*)ap;
                uint2 u8 = *(const uint2*)(ap + 8 * ASP);
                af[mt][0] = u0.x; af[mt][1] = u8.x;
                af[mt][2] = u0.y; af[mt][3] = u8.y;
            }
            uint2 bfr[4];
            #pragma unroll
            for (int nt = 0; nt < 4; nt++)
                bfr[nt] = *(const uint2*)(bs + (ks * 4 + tig) * BSP
                                             + (warpN * 32 + nt * 8 + g) * 2);
            #pragma unroll
            for (int mt = 0; mt < 4; mt++)
                #pragma unroll
                for (int nt = 0; nt < 4; nt++)
                    mma_tf32v(c[mt][nt], af[mt], bfr[nt].x, bfr[nt].y);
        }
        __syncthreads();
    }

    #pragma unroll
    for (int mt = 0; mt < 4; mt++) {
        const int r = row0 + warpM * 64 + mt * 16 + g;
        #pragma unroll
        for (int nt = 0; nt < 4; nt++) {
            const int cc = col0 + warpN * 32 + nt * 8 + 2 * tig;
            const float b0 = bias[cc], b1 = bias[cc + 1];
            *(float2*)(C + (size_t)r * N + cc) =
                make_float2(c[mt][nt][0] + b0, c[mt][nt][1] + b1);
            *(float2*)(C + (size_t)(r + 8) * N + cc) =
                make_float2(c[mt][nt][2] + b0, c[mt][nt][3] + b1);
        }
    }
}

__global__ void __launch_bounds__(256) gemm_tf32_kernel(
    const uint32_t* __restrict__ Ap, const uint32_t* __restrict__ Wp,
    const float* __restrict__ bias, float* __restrict__ C,
    int N, int K)
{
    extern __shared__ uint32_t sm[];
    gemm_body(Ap, Wp, bias, C, N, K, blockIdx.y * 128, blockIdx.x * 128, sm);
}

// Fused K+V projection: grid.x = 8 (4 tiles K, 4 tiles V)
__global__ void __launch_bounds__(256) gemm_tf32_kv_kernel(
    const uint32_t* __restrict__ Ap,
    const uint32_t* __restrict__ Wkp, const float* __restrict__ bk, float* __restrict__ Ck,
    const uint32_t* __restrict__ Wvp, const float* __restrict__ bv, float* __restrict__ Cv,
    int K)
{
    extern __shared__ uint32_t sm[];
    const int bx = blockIdx.x;
    if (bx < 4)
        gemm_body(Ap, Wkp, bk, Ck, KVD, K, blockIdx.y * 128, bx * 128, sm);
    else
        gemm_body(Ap, Wvp, bv, Cv, KVD, K, blockIdx.y * 128, (bx - 4) * 128, sm);
}

// ---------------------------------------------------------------------------
// Fused causal GQA flash attention, TF32 MMA (structure from R4).
// Epilogue writes ao as tf32 bits in (k,k+4)-paired row layout so the Wo GEMM
// consumes it directly with zero conversions (bit-identical numerics).
// ---------------------------------------------------------------------------
#define KST 72
#define VST 72
#define QST 72
#define PST 68
#define ATTN_SMEM_WORDS (64*KST + 64*VST + 128*QST + 128*PST)
#define ATTN_SMEM_BYTES (ATTN_SMEM_WORDS * 4)

__global__ void __launch_bounds__(128) attn_tf32_kernel(
    const float* __restrict__ Q, const float* __restrict__ Kg,
    const float* __restrict__ Vg, float* __restrict__ O)
{
    extern __shared__ uint32_t smu[];
    uint32_t* Ks = smu;
    uint32_t* Vs = Ks + 64 * KST;
    uint32_t* Qs = Vs + 64 * VST;
    uint32_t* Ps = Qs + 128 * QST;

    const int tid  = threadIdx.x;
    const int lane = tid & 31;
    const int warp = tid >> 5;
    const int g    = lane >> 2;
    const int tig  = lane & 3;
    const int wr   = warp * 16;

    const int pr = blockIdx.x;
    const int bh = blockIdx.y;
    const int b  = bh >> 5;
    const int h  = bh & 31;
    const int grp = h >> 2;

    const float* Qb = Q  + (size_t)(b * SS) * DD  + h * HD;
    const float* Kb = Kg + (size_t)(b * SS) * KVD + grp * HD;
    const float* Vb = Vg + (size_t)(b * SS) * KVD + grp * HD;

    for (int halfp = 0; halfp < 2; halfp++) {
        const int Qi = halfp ? (15 - pr) : pr;
        const int q0 = Qi * 128;

        __syncthreads();

        #pragma unroll
        for (int it = 0; it < 8; it++) {
            int idx = it * 128 + tid;
            int r = idx >> 3, c = idx & 7;
            const float* gp = Qb + (size_t)(q0 + r) * DD + c * 8;
            float4 v0 = *(const float4*)gp;
            float4 v1 = *(const float4*)(gp + 4);
            uint32_t* qp = Qs + r * QST + c * 8;
            *(uint4*)qp       = make_uint4(f2tf(v0.x), f2tf(v1.x), f2tf(v0.y), f2tf(v1.y));
            *(uint4*)(qp + 4) = make_uint4(f2tf(v0.z), f2tf(v1.z), f2tf(v0.w), f2tf(v1.w));
        }

        float o[2][8][4];
        float m[2][2], l[2][2];
        #pragma unroll
        for (int rg = 0; rg < 2; rg++) {
            m[rg][0] = -1e30f; m[rg][1] = -1e30f;
            l[rg][0] = 0.0f;   l[rg][1] = 0.0f;
            #pragma unroll
            for (int nt = 0; nt < 8; nt++)
                #pragma unroll
                for (int i = 0; i < 4; i++) o[rg][nt][i] = 0.0f;
        }

        const int tmax = 2 * Qi + 1;
        for (int t = 0; t <= tmax; t++) {
            const int k0 = t * 64;
            __syncthreads();

            #pragma unroll
            for (int it = 0; it < 4; it++) {
                int idx = it * 128 + tid;
                int r = idx >> 3, c = idx & 7;
                const float* gp = Kb + (size_t)(k0 + r) * KVD + c * 8;
                float4 v0 = *(const float4*)gp;
                float4 v1 = *(const float4*)(gp + 4);
                uint32_t* kp = Ks + r * KST + c * 8;
                *(uint4*)kp       = make_uint4(f2tf(v0.x), f2tf(v1.x), f2tf(v0.y), f2tf(v1.y));
                *(uint4*)(kp + 4) = make_uint4(f2tf(v0.z), f2tf(v1.z), f2tf(v0.w), f2tf(v1.w));
            }
            #pragma unroll
            for (int it = 0; it < 8; it++) {
                int idx = it * 128 + tid;
                int r = idx >> 4, dc = (idx & 15) << 2;
                float4 v = *(const float4*)(Vb + (size_t)(k0 + r) * KVD + dc);
                *(uint4*)(Vs + r * VST + dc) =
                    make_uint4(f2tf(v.x), f2tf(v.y), f2tf(v.z), f2tf(v.w));
            }
            __syncthreads();

            float s[2][8][4];
            #pragma unroll
            for (int rg = 0; rg < 2; rg++)
                #pragma unroll
                for (int nt = 0; nt < 8; nt++)
                    #pragma unroll
                    for (int i = 0; i < 4; i++) s[rg][nt][i] = 0.0f;

            #pragma unroll
            for (int ks = 0; ks < 8; ks++) {
                uint32_t af[2][4];
                #pragma unroll
                for (int rg = 0; rg < 2; rg++) {
                    const uint32_t* qp = Qs + (rg * 64 + wr + g) * QST + ks * 8 + 2 * tig;
                    uint2 u0 = *(const uint2*)qp;
                    uint2 u8 = *(const uint2*)(qp + 8 * QST);
                    af[rg][0] = u0.x; af[rg][1] = u8.x;
                    af[rg][2] = u0.y; af[rg][3] = u8.y;
                }
                #pragma unroll
                for (int nt = 0; nt < 8; nt++) {
                    uint2 kb = *(const uint2*)(Ks + (nt * 8 + g) * KST + ks * 8 + 2 * tig);
                    mma_tf32v(s[0][nt], af[0], kb.x, kb.y);
                    mma_tf32v(s[1][nt], af[1], kb.x, kb.y);
                }
            }

            #pragma unroll
            for (int rg = 0; rg < 2; rg++) {
                const bool needmask = (t >= 2 * Qi + rg);
                const int rowg = q0 + rg * 64 + wr + g;
                #pragma unroll
                for (int nt = 0; nt < 8; nt++) {
                    const int cbase = k0 + nt * 8 + 2 * tig;
                    #pragma unroll
                    for (int i = 0; i < 4; i++) {
                        float v = s[rg][nt][i] * 0.125f;
                        if (needmask) {
                            int col = cbase + (i & 1);
                            int row = rowg + ((i & 2) ? 8 : 0);
                            if (col > row) v = -1e30f;
                        }
                        s[rg][nt][i] = v;
                    }
                }

                float r0 = -1e30f, r1 = -1e30f;
                #pragma unroll
                for (int nt = 0; nt < 8; nt++) {
                    r0 = fmaxf(r0, fmaxf(s[rg][nt][0], s[rg][nt][1]));
                    r1 = fmaxf(r1, fmaxf(s[rg][nt][2], s[rg][nt][3]));
                }
                r0 = fmaxf(r0, __shfl_xor_sync(0xffffffffu, r0, 1));
                r0 = fmaxf(r0, __shfl_xor_sync(0xffffffffu, r0, 2));
                r1 = fmaxf(r1, __shfl_xor_sync(0xffffffffu, r1, 1));
                r1 = fmaxf(r1, __shfl_xor_sync(0xffffffffu, r1, 2));

                const float mn0 = fmaxf(m[rg][0], r0), mn1 = fmaxf(m[rg][1], r1);
                const float e0 = __expf(m[rg][0] - mn0), e1 = __expf(m[rg][1] - mn1);
                m[rg][0] = mn0; m[rg][1] = mn1;

                float ls0 = 0.0f, ls1 = 0.0f;
                uint32_t* pbase = Ps + (rg * 64 + wr + g) * PST;
                #pragma unroll
                for (int nt = 0; nt < 8; nt++) {
                    o[rg][nt][0] *= e0; o[rg][nt][1] *= e0;
                    o[rg][nt][2] *= e1; o[rg][nt][3] *= e1;
                    float p0 = __expf(s[rg][nt][0] - mn0);
                    float p1 = __expf(s[rg][nt][1] - mn0);
                    float p2 = __expf(s[rg][nt][2] - mn1);
                    float p3 = __expf(s[rg][nt][3] - mn1);
                    ls0 += p0 + p1; ls1 += p2 + p3;
                    uint32_t* pp = pbase + nt * 8 + 2 * tig;
                    *(uint2*)pp             = make_uint2(f2tf(p0), f2tf(p1));
                    *(uint2*)(pp + 8 * PST) = make_uint2(f2tf(p2), f2tf(p3));
                }
                ls0 += __shfl_xor_sync(0xffffffffu, ls0, 1);
                ls0 += __shfl_xor_sync(0xffffffffu, ls0, 2);
                ls1 += __shfl_xor_sync(0xffffffffu, ls1, 1);
                ls1 += __shfl_xor_sync(0xffffffffu, ls1, 2);
                l[rg][0] = l[rg][0] * e0 + ls0;
                l[rg][1] = l[rg][1] * e1 + ls1;
            }

            __syncwarp();

            #pragma unroll
            for (int ks = 0; ks < 8; ks++) {
                uint32_t pa[2][4];
                #pragma unroll
                for (int rg = 0; rg < 2; rg++) {
                    const uint32_t* pp = Ps + (rg * 64 + wr + g) * PST + ks * 8 + tig;
                    pa[rg][0] = pp[0];
                    pa[rg][1] = pp[8 * PST];
                    pa[rg][2] = pp[4];
                    pa[rg][3] = pp[8 * PST + 4];
                }
                #pragma unroll
                for (int nt = 0; nt < 8; nt++) {
                    const uint32_t* vp = Vs + (ks * 8 + tig) * VST + nt * 8 + g;
                    const uint32_t b0 = vp[0];
                    const uint32_t b1 = vp[4 * VST];
                    mma_tf32v(o[0][nt], pa[0], b0, b1);
                    mma_tf32v(o[1][nt], pa[1], b0, b1);
                }
            }
        }

        // ---- epilogue: normalize, tf32-round, store in paired-row layout ----
        // col j within 8-group maps to word 2*(j&3)+(j>>2).
        // lane's cols j0=2*tig, j0+1 -> words w0, w0+2 with:
        const int w0 = 4 * (tig & 1) + (tig >> 1);
        #pragma unroll
        for (int rg = 0; rg < 2; rg++) {
            const float inv0 = 1.0f / l[rg][0], inv1 = 1.0f / l[rg][1];
            float* Ob = O + (size_t)(b * SS + q0 + rg * 64 + wr + g) * DD + h * HD;
            #pragma unroll
            for (int nt = 0; nt < 8; nt++) {
                float* p0 = Ob + nt * 8;
                float* p8 = Ob + 8 * DD + nt * 8;
                p0[w0]     = __uint_as_float(f2tf(o[rg][nt][0] * inv0));
                p0[w0 + 2] = __uint_as_float(f2tf(o[rg][nt][1] * inv0));
                p8[w0]     = __uint_as_float(f2tf(o[rg][nt][2] * inv1));
                p8[w0 + 2] = __uint_as_float(f2tf(o[rg][nt][3] * inv1));
            }
        }
    }
}

// ---------------------------------------------------------------------------
// Launch
// ---------------------------------------------------------------------------
extern "C" void kernel_launch(void* const* d_in, const int* in_sizes, int n_in,
                              void* d_out, int out_size)
{
    (void)in_sizes; (void)n_in; (void)out_size;
    const float* x  = (const float*)d_in[0];
    const float* kv = (const float*)d_in[1];
    const float* Wq = (const float*)d_in[2];
    const float* bq = (const float*)d_in[3];
    const float* Wk = (const float*)d_in[4];
    const float* bk = (const float*)d_in[5];
    const float* Wv = (const float*)d_in[6];
    const float* bv = (const float*)d_in[7];
    const float* Wo = (const float*)d_in[8];
    const float* bo = (const float*)d_in[9];
    float* out = (float*)d_out;

    float *q, *k, *v, *ao;
    uint32_t *xp, *kvp, *wqp, *wkp, *wvp, *wop;
    cudaGetSymbolAddress((void**)&q,   g_q);
    cudaGetSymbolAddress((void**)&k,   g_k);
    cudaGetSymbolAddress((void**)&v,   g_v);
    cudaGetSymbolAddress((void**)&ao,  g_ao);
    cudaGetSymbolAddress((void**)&xp,  g_xp);
    cudaGetSymbolAddress((void**)&kvp, g_kvp);
    cudaGetSymbolAddress((void**)&wqp, g_wqp);
    cudaGetSymbolAddress((void**)&wkp, g_wkp);
    cudaGetSymbolAddress((void**)&wvp, g_wvp);
    cudaGetSymbolAddress((void**)&wop, g_wop);

    cudaFuncSetAttribute(gemm_tf32_kernel,
                         cudaFuncAttributeMaxDynamicSharedMemorySize,
                         GEMM_SMEM_BYTES);
    cudaFuncSetAttribute(gemm_tf32_kv_kernel,
                         cudaFuncAttributeMaxDynamicSharedMemorySize,
                         GEMM_SMEM_BYTES);
    cudaFuncSetAttribute(attn_tf32_kernel,
                         cudaFuncAttributeMaxDynamicSharedMemorySize,
                         ATTN_SMEM_BYTES);

    // pre-passes: tf32 convert + pair
    pair_rows_kernel<<<MTOT * DD / 8 / 256, 256>>>((const float4*)x,  (uint4*)xp);
    pair_rows_kernel<<<MTOT * DD / 8 / 256, 256>>>((const float4*)kv, (uint4*)kvp);
    pair_weights_kernel<<<(DD/2) * (DD/4)  / 256, 256>>>(Wq, wqp, DD);
    pair_weights_kernel<<<(DD/2) * (KVD/4) / 256, 256>>>(Wk, wkp, KVD);
    pair_weights_kernel<<<(DD/2) * (KVD/4) / 256, 256>>>(Wv, wvp, KVD);
    pair_weights_kernel<<<(DD/2) * (DD/4)  / 256, 256>>>(Wo, wop, DD);

    // projections
    gemm_tf32_kernel<<<dim3(DD / 128, MTOT / 128), 256, GEMM_SMEM_BYTES>>>(
        xp, wqp, bq, q, DD, DD);
    gemm_tf32_kv_kernel<<<dim3(8, MTOT / 128), 256, GEMM_SMEM_BYTES>>>(
        kvp, wkp, bk, k, wvp, bv, v, DD);

    // fused causal GQA attention (writes tf32-paired ao)
    attn_tf32_kernel<<<dim3(8, BB * HH), 128, ATTN_SMEM_BYTES>>>(q, k, v, ao);

    // output projection (consumes pre-paired ao directly)
    gemm_tf32_kernel<<<dim3(DD / 128, MTOT / 128), 256, GEMM_SMEM_BYTES>>>(
        (const uint32_t*)ao, wop, bo, out, DD, DD);
}

// round 8
// speedup vs baseline: 3.7383x; 1.0324x over previous
#include <cuda_runtime.h>
#include <math.h>
#include <stdint.h>

// Problem constants (fixed shapes)
#define BB 2
#define SS 2048
#define DD 2048
#define HH 32
#define GG 8
#define HD 64
#define KVD 512        // G*HD
#define MTOT (BB*SS)   // 4096

// Scratch (static device globals; no allocation allowed)
__device__ float    g_q  [MTOT*DD];
__device__ float    g_k  [MTOT*KVD];
__device__ float    g_v  [MTOT*KVD];
__device__ float    g_ao [MTOT*DD];   // attention out: tf32 bits, (k,k+4)-paired rows
__device__ uint32_t g_xp [MTOT*DD];   // x,  tf32 + paired rows
__device__ uint32_t g_kvp[MTOT*DD];   // kv, tf32 + paired rows
__device__ uint32_t g_wqp[DD*DD];     // weights: tf32, pair-row interleaved [K/2][N][2]
__device__ uint32_t g_wkp[DD*KVD];
__device__ uint32_t g_wvp[DD*KVD];
__device__ uint32_t g_wop[DD*DD];

// ---------------------------------------------------------------------------
// helpers
// ---------------------------------------------------------------------------
__device__ __forceinline__ uint32_t f2tf(float x) {
    uint32_t r;
    asm("cvt.rna.tf32.f32 %0, %1;" : "=r"(r) : "f"(x));
    return r;
}
__device__ __forceinline__ uint32_t sptr(const void* p) {
    return (uint32_t)__cvta_generic_to_shared(p);
}
__device__ __forceinline__ void cpa16(uint32_t s, const void* g) {
    asm volatile("cp.async.cg.shared.global [%0], [%1], 16;" :: "r"(s), "l"(g));
}
#define CP_COMMIT() asm volatile("cp.async.commit_group;")
#define CP_WAIT(N)  asm volatile("cp.async.wait_group %0;" :: "n"(N))

__device__ __forceinline__ void mma_tf32(
    float& c0, float& c1, float& c2, float& c3,
    uint32_t a0, uint32_t a1, uint32_t a2, uint32_t a3,
    uint32_t b0, uint32_t b1)
{
    asm volatile(
        "mma.sync.aligned.m16n8k8.row.col.f32.tf32.tf32.f32 "
        "{%0,%1,%2,%3}, {%4,%5,%6,%7}, {%8,%9}, {%0,%1,%2,%3};"
        : "+f"(c0), "+f"(c1), "+f"(c2), "+f"(c3)
        : "r"(a0), "r"(a1), "r"(a2), "r"(a3), "r"(b0), "r"(b1));
}
__device__ __forceinline__ void mma_tf32v(float c[4], const uint32_t a[4],
                                          uint32_t b0, uint32_t b1)
{
    mma_tf32(c[0], c[1], c[2], c[3], a[0], a[1], a[2], a[3], b0, b1);
}

// ---------------------------------------------------------------------------
// Pre-pass kernels: tf32-convert + pair once (bit-identical to fragment cvt).
// ---------------------------------------------------------------------------
__global__ void __launch_bounds__(256) pair_rows_kernel(
    const float4* __restrict__ in, uint4* __restrict__ out)
{
    const int idx = blockIdx.x * 256 + threadIdx.x;   // one 8-float group
    const float4 v0 = in[idx * 2];
    const float4 v1 = in[idx * 2 + 1];
    out[idx * 2]     = make_uint4(f2tf(v0.x), f2tf(v1.x), f2tf(v0.y), f2tf(v1.y));
    out[idx * 2 + 1] = make_uint4(f2tf(v0.z), f2tf(v1.z), f2tf(v0.w), f2tf(v1.w));
}

__global__ void __launch_bounds__(256) pair_weights_kernel(
    const float* __restrict__ W, uint32_t* __restrict__ Wp, int N)
{
    const int idx = blockIdx.x * 256 + threadIdx.x;
    const int ncq = N >> 2;
    const int p   = idx / ncq;          // pair index 0..K/2-1  (K=2048)
    const int nc  = idx - p * ncq;
    const int klo = (p >> 2) * 8 + (p & 3);
    const float4 lo = *(const float4*)(W + (size_t)klo * N + nc * 4);
    const float4 hi = *(const float4*)(W + (size_t)(klo + 4) * N + nc * 4);
    uint4* op = (uint4*)(Wp + (size_t)p * (2 * N) + nc * 8);
    op[0] = make_uint4(f2tf(lo.x), f2tf(hi.x), f2tf(lo.y), f2tf(hi.y));
    op[1] = make_uint4(f2tf(lo.z), f2tf(hi.z), f2tf(lo.w), f2tf(hi.w));
}

// ---------------------------------------------------------------------------
// TF32 GEMM + bias on pre-converted/pre-paired operands.
// 128x128x32 tile, 256 threads, cp.async double buffer.
// Single __syncthreads per K-chunk; fragment double-buffering across ks.
// ---------------------------------------------------------------------------
#define ASP 40     // A smem row stride (32 + 8 pad); a-frag banks CF
#define BSP 264    // B smem pair-row stride (256 + 8); b-frag banks CF
#define GEMM_BUF_WORDS (128*ASP + 16*BSP)
#define GEMM_SMEM_BYTES (2 * GEMM_BUF_WORDS * 4)

#define GSTAGE(asb, bsb, ktc) do {                                          \
    const int _kb = (ktc) << 5;                                             \
    const int _pg = (ktc) << 4;                                             \
    _Pragma("unroll")                                                       \
    for (int _it = 0; _it < 4; _it++) {                                     \
        int _idx = _it * 256 + tid;                                         \
        int _r = _idx >> 3, _w = (_idx & 7) << 2;                           \
        cpa16(sptr((asb) + _r * ASP + _w),                                  \
              Ap + (size_t)(row0 + _r) * K + _kb + _w);                     \
    }                                                                       \
    _Pragma("unroll")                                                       \
    for (int _it = 0; _it < 4; _it++) {                                     \
        int _idx = _it * 256 + tid;                                         \
        int _pr = _idx >> 6, _w = (_idx & 63) << 2;                         \
        cpa16(sptr((bsb) + _pr * BSP + _w),                                 \
              Wp + (size_t)(_pg + _pr) * wrow + col0 * 2 + _w);             \
    }                                                                       \
} while(0)

#define GLOADFRAG(ksv, afA, bfA) do {                                       \
    _Pragma("unroll")                                                       \
    for (int _mt = 0; _mt < 4; _mt++) {                                     \
        const uint32_t* _ap = as + (warpM * 64 + _mt * 16 + g) * ASP        \
                                 + (ksv) * 8 + 2 * tig;                     \
        uint2 _u0 = *(const uint2*)_ap;                                     \
        uint2 _u8 = *(const uint2*)(_ap + 8 * ASP);                         \
        (afA)[_mt][0] = _u0.x; (afA)[_mt][1] = _u8.x;                       \
        (afA)[_mt][2] = _u0.y; (afA)[_mt][3] = _u8.y;                       \
    }                                                                       \
    _Pragma("unroll")                                                       \
    for (int _nt = 0; _nt < 4; _nt++)                                       \
        (bfA)[_nt] = *(const uint2*)(bs + ((ksv) * 4 + tig) * BSP           \
                                        + (warpN * 32 + _nt * 8 + g) * 2);  \
} while(0)

__device__ __forceinline__ void gemm_body(
    const uint32_t* __restrict__ Ap, const uint32_t* __restrict__ Wp,
    const float* __restrict__ bias, float* __restrict__ C,
    int N, int K, int row0, int col0, uint32_t* sm)
{
    uint32_t* As0 = sm;
    uint32_t* Bs0 = As0 + 128 * ASP;
    uint32_t* As1 = Bs0 + 16 * BSP;
    uint32_t* Bs1 = As1 + 128 * ASP;

    const int tid  = threadIdx.x;
    const int lane = tid & 31;
    const int warp = tid >> 5;
    const int g    = lane >> 2;
    const int tig  = lane & 3;
    const int warpM = warp >> 2;
    const int warpN = warp & 3;

    float c[4][4][4];
    #pragma unroll
    for (int i = 0; i < 4; i++)
        #pragma unroll
        for (int j = 0; j < 4; j++)
            #pragma unroll
            for (int r = 0; r < 4; r++) c[i][j][r] = 0.0f;

    const int nk = K >> 5;
    const size_t wrow = (size_t)(2 * N);

    // prologue: chunk 0 -> buffer 0
    GSTAGE(As0, Bs0, 0);
    CP_COMMIT();

    for (int kt = 0; kt < nk; kt++) {
        CP_WAIT(0);
        __syncthreads();   // chunk kt visible; all warps done reading other buf

        if (kt + 1 < nk) {
            if ((kt + 1) & 1) GSTAGE(As1, Bs1, kt + 1);
            else              GSTAGE(As0, Bs0, kt + 1);
            CP_COMMIT();
        }

        const uint32_t* as = (kt & 1) ? As1 : As0;
        const uint32_t* bs = (kt & 1) ? Bs1 : Bs0;

        uint32_t af[2][4][4];
        uint2    bf[2][4];
        GLOADFRAG(0, af[0], bf[0]);

        #pragma unroll
        for (int ks = 0; ks < 4; ks++) {
            const int cu = ks & 1;
            if (ks < 3) GLOADFRAG(ks + 1, af[cu ^ 1], bf[cu ^ 1]);
            #pragma unroll
            for (int mt = 0; mt < 4; mt++)
                #pragma unroll
                for (int nt = 0; nt < 4; nt++)
                    mma_tf32v(c[mt][nt], af[cu][mt], bf[cu][nt].x, bf[cu][nt].y);
        }
    }

    #pragma unroll
    for (int mt = 0; mt < 4; mt++) {
        const int r = row0 + warpM * 64 + mt * 16 + g;
        #pragma unroll
        for (int nt = 0; nt < 4; nt++) {
            const int cc = col0 + warpN * 32 + nt * 8 + 2 * tig;
            const float b0 = bias[cc], b1 = bias[cc + 1];
            *(float2*)(C + (size_t)r * N + cc) =
                make_float2(c[mt][nt][0] + b0, c[mt][nt][1] + b1);
            *(float2*)(C + (size_t)(r + 8) * N + cc) =
                make_float2(c[mt][nt][2] + b0, c[mt][nt][3] + b1);
        }
    }
}

__global__ void __launch_bounds__(256, 2) gemm_tf32_kernel(
    const uint32_t* __restrict__ Ap, const uint32_t* __restrict__ Wp,
    const float* __restrict__ bias, float* __restrict__ C,
    int N, int K)
{
    extern __shared__ uint32_t sm[];
    gemm_body(Ap, Wp, bias, C, N, K, blockIdx.y * 128, blockIdx.x * 128, sm);
}

// Fused Q+K+V projections: grid.x = 24 (16 Q tiles, 4 K, 4 V), one wave pool.
__global__ void __launch_bounds__(256, 2) gemm_tf32_qkv_kernel(
    const uint32_t* __restrict__ xp,  const uint32_t* __restrict__ kvp,
    const uint32_t* __restrict__ wqp, const float* __restrict__ bq, float* __restrict__ q,
    const uint32_t* __restrict__ wkp, const float* __restrict__ bk, float* __restrict__ k,
    const uint32_t* __restrict__ wvp, const float* __restrict__ bv, float* __restrict__ v)
{
    extern __shared__ uint32_t sm[];
    const int bx = blockIdx.x;
    const uint32_t *Ax, *Wx;
    const float* bx_;
    float* Cx;
    int Nx, c0;
    if (bx < 16)      { Ax = xp;  Wx = wqp; bx_ = bq; Cx = q; Nx = DD;  c0 = bx * 128; }
    else if (bx < 20) { Ax = kvp; Wx = wkp; bx_ = bk; Cx = k; Nx = KVD; c0 = (bx - 16) * 128; }
    else              { Ax = kvp; Wx = wvp; bx_ = bv; Cx = v; Nx = KVD; c0 = (bx - 20) * 128; }
    gemm_body(Ax, Wx, bx_, Cx, Nx, DD, blockIdx.y * 128, c0, sm);
}

// ---------------------------------------------------------------------------
// Fused causal GQA flash attention, TF32 MMA (unchanged from 1009.8 version).
// Epilogue writes ao as tf32 bits in (k,k+4)-paired row layout for Wo GEMM.
// ---------------------------------------------------------------------------
#define KST 72
#define VST 72
#define QST 72
#define PST 68
#define ATTN_SMEM_WORDS (64*KST + 64*VST + 128*QST + 128*PST)
#define ATTN_SMEM_BYTES (ATTN_SMEM_WORDS * 4)

__global__ void __launch_bounds__(128) attn_tf32_kernel(
    const float* __restrict__ Q, const float* __restrict__ Kg,
    const float* __restrict__ Vg, float* __restrict__ O)
{
    extern __shared__ uint32_t smu[];
    uint32_t* Ks = smu;
    uint32_t* Vs = Ks + 64 * KST;
    uint32_t* Qs = Vs + 64 * VST;
    uint32_t* Ps = Qs + 128 * QST;

    const int tid  = threadIdx.x;
    const int lane = tid & 31;
    const int warp = tid >> 5;
    const int g    = lane >> 2;
    const int tig  = lane & 3;
    const int wr   = warp * 16;

    const int pr = blockIdx.x;
    const int bh = blockIdx.y;
    const int b  = bh >> 5;
    const int h  = bh & 31;
    const int grp = h >> 2;

    const float* Qb = Q  + (size_t)(b * SS) * DD  + h * HD;
    const float* Kb = Kg + (size_t)(b * SS) * KVD + grp * HD;
    const float* Vb = Vg + (size_t)(b * SS) * KVD + grp * HD;

    for (int halfp = 0; halfp < 2; halfp++) {
        const int Qi = halfp ? (15 - pr) : pr;
        const int q0 = Qi * 128;

        __syncthreads();

        #pragma unroll
        for (int it = 0; it < 8; it++) {
            int idx = it * 128 + tid;
            int r = idx >> 3, c = idx & 7;
            const float* gp = Qb + (size_t)(q0 + r) * DD + c * 8;
            float4 v0 = *(const float4*)gp;
            float4 v1 = *(const float4*)(gp + 4);
            uint32_t* qp = Qs + r * QST + c * 8;
            *(uint4*)qp       = make_uint4(f2tf(v0.x), f2tf(v1.x), f2tf(v0.y), f2tf(v1.y));
            *(uint4*)(qp + 4) = make_uint4(f2tf(v0.z), f2tf(v1.z), f2tf(v0.w), f2tf(v1.w));
        }

        float o[2][8][4];
        float m[2][2], l[2][2];
        #pragma unroll
        for (int rg = 0; rg < 2; rg++) {
            m[rg][0] = -1e30f; m[rg][1] = -1e30f;
            l[rg][0] = 0.0f;   l[rg][1] = 0.0f;
            #pragma unroll
            for (int nt = 0; nt < 8; nt++)
                #pragma unroll
                for (int i = 0; i < 4; i++) o[rg][nt][i] = 0.0f;
        }

        const int tmax = 2 * Qi + 1;
        for (int t = 0; t <= tmax; t++) {
            const int k0 = t * 64;
            __syncthreads();

            #pragma unroll
            for (int it = 0; it < 4; it++) {
                int idx = it * 128 + tid;
                int r = idx >> 3, c = idx & 7;
                const float* gp = Kb + (size_t)(k0 + r) * KVD + c * 8;
                float4 v0 = *(const float4*)gp;
                float4 v1 = *(const float4*)(gp + 4);
                uint32_t* kp = Ks + r * KST + c * 8;
                *(uint4*)kp       = make_uint4(f2tf(v0.x), f2tf(v1.x), f2tf(v0.y), f2tf(v1.y));
                *(uint4*)(kp + 4) = make_uint4(f2tf(v0.z), f2tf(v1.z), f2tf(v0.w), f2tf(v1.w));
            }
            #pragma unroll
            for (int it = 0; it < 8; it++) {
                int idx = it * 128 + tid;
                int r = idx >> 4, dc = (idx & 15) << 2;
                float4 v = *(const float4*)(Vb + (size_t)(k0 + r) * KVD + dc);
                *(uint4*)(Vs + r * VST + dc) =
                    make_uint4(f2tf(v.x), f2tf(v.y), f2tf(v.z), f2tf(v.w));
            }
            __syncthreads();

            float s[2][8][4];
            #pragma unroll
            for (int rg = 0; rg < 2; rg++)
                #pragma unroll
                for (int nt = 0; nt < 8; nt++)
                    #pragma unroll
                    for (int i = 0; i < 4; i++) s[rg][nt][i] = 0.0f;

            #pragma unroll
            for (int ks = 0; ks < 8; ks++) {
                uint32_t af[2][4];
                #pragma unroll
                for (int rg = 0; rg < 2; rg++) {
                    const uint32_t* qp = Qs + (rg * 64 + wr + g) * QST + ks * 8 + 2 * tig;
                    uint2 u0 = *(const uint2*)qp;
                    uint2 u8 = *(const uint2*)(qp + 8 * QST);
                    af[rg][0] = u0.x; af[rg][1] = u8.x;
                    af[rg][2] = u0.y; af[rg][3] = u8.y;
                }
                #pragma unroll
                for (int nt = 0; nt < 8; nt++) {
                    uint2 kb = *(const uint2*)(Ks + (nt * 8 + g) * KST + ks * 8 + 2 * tig);
                    mma_tf32v(s[0][nt], af[0], kb.x, kb.y);
                    mma_tf32v(s[1][nt], af[1], kb.x, kb.y);
                }
            }

            #pragma unroll
            for (int rg = 0; rg < 2; rg++) {
                const bool needmask = (t >= 2 * Qi + rg);
                const int rowg = q0 + rg * 64 + wr + g;
                #pragma unroll
                for (int nt = 0; nt < 8; nt++) {
                    const int cbase = k0 + nt * 8 + 2 * tig;
                    #pragma unroll
                    for (int i = 0; i < 4; i++) {
                        float v = s[rg][nt][i] * 0.125f;
                        if (needmask) {
                            int col = cbase + (i & 1);
                            int row = rowg + ((i & 2) ? 8 : 0);
                            if (col > row) v = -1e30f;
                        }
                        s[rg][nt][i] = v;
                    }
                }

                float r0 = -1e30f, r1 = -1e30f;
                #pragma unroll
                for (int nt = 0; nt < 8; nt++) {
                    r0 = fmaxf(r0, fmaxf(s[rg][nt][0], s[rg][nt][1]));
                    r1 = fmaxf(r1, fmaxf(s[rg][nt][2], s[rg][nt][3]));
                }
                r0 = fmaxf(r0, __shfl_xor_sync(0xffffffffu, r0, 1));
                r0 = fmaxf(r0, __shfl_xor_sync(0xffffffffu, r0, 2));
                r1 = fmaxf(r1, __shfl_xor_sync(0xffffffffu, r1, 1));
                r1 = fmaxf(r1, __shfl_xor_sync(0xffffffffu, r1, 2));

                const float mn0 = fmaxf(m[rg][0], r0), mn1 = fmaxf(m[rg][1], r1);
                const float e0 = __expf(m[rg][0] - mn0), e1 = __expf(m[rg][1] - mn1);
                m[rg][0] = mn0; m[rg][1] = mn1;

                float ls0 = 0.0f, ls1 = 0.0f;
                uint32_t* pbase = Ps + (rg * 64 + wr + g) * PST;
                #pragma unroll
                for (int nt = 0; nt < 8; nt++) {
                    o[rg][nt][0] *= e0; o[rg][nt][1] *= e0;
                    o[rg][nt][2] *= e1; o[rg][nt][3] *= e1;
                    float p0 = __expf(s[rg][nt][0] - mn0);
                    float p1 = __expf(s[rg][nt][1] - mn0);
                    float p2 = __expf(s[rg][nt][2] - mn1);
                    float p3 = __expf(s[rg][nt][3] - mn1);
                    ls0 += p0 + p1; ls1 += p2 + p3;
                    uint32_t* pp = pbase + nt * 8 + 2 * tig;
                    *(uint2*)pp             = make_uint2(f2tf(p0), f2tf(p1));
                    *(uint2*)(pp + 8 * PST) = make_uint2(f2tf(p2), f2tf(p3));
                }
                ls0 += __shfl_xor_sync(0xffffffffu, ls0, 1);
                ls0 += __shfl_xor_sync(0xffffffffu, ls0, 2);
                ls1 += __shfl_xor_sync(0xffffffffu, ls1, 1);
                ls1 += __shfl_xor_sync(0xffffffffu, ls1, 2);
                l[rg][0] = l[rg][0] * e0 + ls0;
                l[rg][1] = l[rg][1] * e1 + ls1;
            }

            __syncwarp();

            #pragma unroll
            for (int ks = 0; ks < 8; ks++) {
                uint32_t pa[2][4];
                #pragma unroll
                for (int rg = 0; rg < 2; rg++) {
                    const uint32_t* pp = Ps + (rg * 64 + wr + g) * PST + ks * 8 + tig;
                    pa[rg][0] = pp[0];
                    pa[rg][1] = pp[8 * PST];
                    pa[rg][2] = pp[4];
                    pa[rg][3] = pp[8 * PST + 4];
                }
                #pragma unroll
                for (int nt = 0; nt < 8; nt++) {
                    const uint32_t* vp = Vs + (ks * 8 + tig) * VST + nt * 8 + g;
                    const uint32_t b0 = vp[0];
                    const uint32_t b1 = vp[4 * VST];
                    mma_tf32v(o[0][nt], pa[0], b0, b1);
                    mma_tf32v(o[1][nt], pa[1], b0, b1);
                }
            }
        }

        // epilogue: normalize, tf32-round, store in paired-row layout
        const int w0 = 4 * (tig & 1) + (tig >> 1);
        #pragma unroll
        for (int rg = 0; rg < 2; rg++) {
            const float inv0 = 1.0f / l[rg][0], inv1 = 1.0f / l[rg][1];
            float* Ob = O + (size_t)(b * SS + q0 + rg * 64 + wr + g) * DD + h * HD;
            #pragma unroll
            for (int nt = 0; nt < 8; nt++) {
                float* p0 = Ob + nt * 8;
                float* p8 = Ob + 8 * DD + nt * 8;
                p0[w0]     = __uint_as_float(f2tf(o[rg][nt][0] * inv0));
                p0[w0 + 2] = __uint_as_float(f2tf(o[rg][nt][1] * inv0));
                p8[w0]     = __uint_as_float(f2tf(o[rg][nt][2] * inv1));
                p8[w0 + 2] = __uint_as_float(f2tf(o[rg][nt][3] * inv1));
            }
        }
    }
}

// ---------------------------------------------------------------------------
// Launch
// ---------------------------------------------------------------------------
extern "C" void kernel_launch(void* const* d_in, const int* in_sizes, int n_in,
                              void* d_out, int out_size)
{
    (void)in_sizes; (void)n_in; (void)out_size;
    const float* x  = (const float*)d_in[0];
    const float* kv = (const float*)d_in[1];
    const float* Wq = (const float*)d_in[2];
    const float* bq = (const float*)d_in[3];
    const float* Wk = (const float*)d_in[4];
    const float* bk = (const float*)d_in[5];
    const float* Wv = (const float*)d_in[6];
    const float* bv = (const float*)d_in[7];
    const float* Wo = (const float*)d_in[8];
    const float* bo = (const float*)d_in[9];
    float* out = (float*)d_out;

    float *q, *k, *v, *ao;
    uint32_t *xp, *kvp, *wqp, *wkp, *wvp, *wop;
    cudaGetSymbolAddress((void**)&q,   g_q);
    cudaGetSymbolAddress((void**)&k,   g_k);
    cudaGetSymbolAddress((void**)&v,   g_v);
    cudaGetSymbolAddress((void**)&ao,  g_ao);
    cudaGetSymbolAddress((void**)&xp,  g_xp);
    cudaGetSymbolAddress((void**)&kvp, g_kvp);
    cudaGetSymbolAddress((void**)&wqp, g_wqp);
    cudaGetSymbolAddress((void**)&wkp, g_wkp);
    cudaGetSymbolAddress((void**)&wvp, g_wvp);
    cudaGetSymbolAddress((void**)&wop, g_wop);

    cudaFuncSetAttribute(gemm_tf32_kernel,
                         cudaFuncAttributeMaxDynamicSharedMemorySize,
                         GEMM_SMEM_BYTES);
    cudaFuncSetAttribute(gemm_tf32_qkv_kernel,
                         cudaFuncAttributeMaxDynamicSharedMemorySize,
                         GEMM_SMEM_BYTES);
    cudaFuncSetAttribute(attn_tf32_kernel,
                         cudaFuncAttributeMaxDynamicSharedMemorySize,
                         ATTN_SMEM_BYTES);

    // pre-passes: tf32 convert + pair
    pair_rows_kernel<<<MTOT * DD / 8 / 256, 256>>>((const float4*)x,  (uint4*)xp);
    pair_rows_kernel<<<MTOT * DD / 8 / 256, 256>>>((const float4*)kv, (uint4*)kvp);
    pair_weights_kernel<<<(DD/2) * (DD/4)  / 256, 256>>>(Wq, wqp, DD);
    pair_weights_kernel<<<(DD/2) * (KVD/4) / 256, 256>>>(Wk, wkp, KVD);
    pair_weights_kernel<<<(DD/2) * (KVD/4) / 256, 256>>>(Wv, wvp, KVD);
    pair_weights_kernel<<<(DD/2) * (DD/4)  / 256, 256>>>(Wo, wop, DD);

    // fused Q+K+V projections (one wave pool, 768 CTAs)
    gemm_tf32_qkv_kernel<<<dim3(24, MTOT / 128), 256, GEMM_SMEM_BYTES>>>(
        xp, kvp, wqp, bq, q, wkp, bk, k, wvp, bv, v);

    // fused causal GQA attention (writes tf32-paired ao)
    attn_tf32_kernel<<<dim3(8, BB * HH), 128, ATTN_SMEM_BYTES>>>(q, k, v, ao);

    // output projection (consumes pre-paired ao directly)
    gemm_tf32_kernel<<<dim3(DD / 128, MTOT / 128), 256, GEMM_SMEM_BYTES>>>(
        (const uint32_t*)ao, wop, bo, out, DD, DD);
}

// round 9
// speedup vs baseline: 3.7644x; 1.0070x over previous
#include <cuda_runtime.h>
#include <math.h>
#include <stdint.h>

// Problem constants (fixed shapes)
#define BB 2
#define SS 2048
#define DD 2048
#define HH 32
#define GG 8
#define HD 64
#define KVD 512        // G*HD
#define MTOT (BB*SS)   // 4096

// Scratch (static device globals; no allocation allowed)
__device__ uint32_t g_q  [MTOT*DD];    // Q proj: tf32 bits, paired word order
__device__ uint32_t g_k  [MTOT*KVD];   // K proj: tf32 bits, paired word order
__device__ uint32_t g_v  [MTOT*KVD];   // V proj: tf32 bits, natural order
__device__ float    g_ao [MTOT*DD];    // attention out: tf32 bits, paired rows
__device__ uint32_t g_xp [MTOT*DD];    // x,  tf32 + paired rows
__device__ uint32_t g_kvp[MTOT*DD];    // kv, tf32 + paired rows
__device__ uint32_t g_wqp[DD*DD];      // weights: tf32, pair-row interleaved
__device__ uint32_t g_wkp[DD*KVD];
__device__ uint32_t g_wvp[DD*KVD];
__device__ uint32_t g_wop[DD*DD];

// ---------------------------------------------------------------------------
// helpers
// ---------------------------------------------------------------------------
__device__ __forceinline__ uint32_t f2tf(float x) {
    uint32_t r;
    asm("cvt.rna.tf32.f32 %0, %1;" : "=r"(r) : "f"(x));
    return r;
}
__device__ __forceinline__ uint32_t sptr(const void* p) {
    return (uint32_t)__cvta_generic_to_shared(p);
}
__device__ __forceinline__ void cpa16(uint32_t s, const void* g) {
    asm volatile("cp.async.cg.shared.global [%0], [%1], 16;" :: "r"(s), "l"(g));
}
#define CP_COMMIT() asm volatile("cp.async.commit_group;")
#define CP_WAIT(N)  asm volatile("cp.async.wait_group %0;" :: "n"(N))

__device__ __forceinline__ void mma_tf32(
    float& c0, float& c1, float& c2, float& c3,
    uint32_t a0, uint32_t a1, uint32_t a2, uint32_t a3,
    uint32_t b0, uint32_t b1)
{
    asm volatile(
        "mma.sync.aligned.m16n8k8.row.col.f32.tf32.tf32.f32 "
        "{%0,%1,%2,%3}, {%4,%5,%6,%7}, {%8,%9}, {%0,%1,%2,%3};"
        : "+f"(c0), "+f"(c1), "+f"(c2), "+f"(c3)
        : "r"(a0), "r"(a1), "r"(a2), "r"(a3), "r"(b0), "r"(b1));
}
__device__ __forceinline__ void mma_tf32v(float c[4], const uint32_t a[4],
                                          uint32_t b0, uint32_t b1)
{
    mma_tf32(c[0], c[1], c[2], c[3], a[0], a[1], a[2], a[3], b0, b1);
}

// ---------------------------------------------------------------------------
// Pre-pass kernels (unchanged, bit-identical)
// ---------------------------------------------------------------------------
__global__ void __launch_bounds__(256) pair_rows_kernel(
    const float4* __restrict__ in, uint4* __restrict__ out)
{
    const int idx = blockIdx.x * 256 + threadIdx.x;
    const float4 v0 = in[idx * 2];
    const float4 v1 = in[idx * 2 + 1];
    out[idx * 2]     = make_uint4(f2tf(v0.x), f2tf(v1.x), f2tf(v0.y), f2tf(v1.y));
    out[idx * 2 + 1] = make_uint4(f2tf(v0.z), f2tf(v1.z), f2tf(v0.w), f2tf(v1.w));
}

__global__ void __launch_bounds__(256) pair_weights_kernel(
    const float* __restrict__ W, uint32_t* __restrict__ Wp, int N)
{
    const int idx = blockIdx.x * 256 + threadIdx.x;
    const int ncq = N >> 2;
    const int p   = idx / ncq;
    const int nc  = idx - p * ncq;
    const int klo = (p >> 2) * 8 + (p & 3);
    const float4 lo = *(const float4*)(W + (size_t)klo * N + nc * 4);
    const float4 hi = *(const float4*)(W + (size_t)(klo + 4) * N + nc * 4);
    uint4* op = (uint4*)(Wp + (size_t)p * (2 * N) + nc * 8);
    op[0] = make_uint4(f2tf(lo.x), f2tf(hi.x), f2tf(lo.y), f2tf(hi.y));
    op[1] = make_uint4(f2tf(lo.z), f2tf(hi.z), f2tf(lo.w), f2tf(hi.w));
}

// ---------------------------------------------------------------------------
// TF32 GEMM + bias, templated epilogue:
//   EM=0: fp32 natural   EM=1: tf32 bits, paired word order   EM=2: tf32 natural
// ---------------------------------------------------------------------------
#define ASP 40
#define BSP 264
#define GEMM_BUF_WORDS (128*ASP + 16*BSP)
#define GEMM_SMEM_BYTES (2 * GEMM_BUF_WORDS * 4)

#define GSTAGE(asb, bsb, ktc) do {                                          \
    const int _kb = (ktc) << 5;                                             \
    const int _pg = (ktc) << 4;                                             \
    _Pragma("unroll")                                                       \
    for (int _it = 0; _it < 4; _it++) {                                     \
        int _idx = _it * 256 + tid;                                         \
        int _r = _idx >> 3, _w = (_idx & 7) << 2;                           \
        cpa16(sptr((asb) + _r * ASP + _w),                                  \
              Ap + (size_t)(row0 + _r) * K + _kb + _w);                     \
    }                                                                       \
    _Pragma("unroll")                                                       \
    for (int _it = 0; _it < 4; _it++) {                                     \
        int _idx = _it * 256 + tid;                                         \
        int _pr = _idx >> 6, _w = (_idx & 63) << 2;                         \
        cpa16(sptr((bsb) + _pr * BSP + _w),                                 \
              Wp + (size_t)(_pg + _pr) * wrow + col0 * 2 + _w);             \
    }                                                                       \
} while(0)

#define GLOADFRAG(ksv, afA, bfA) do {                                       \
    _Pragma("unroll")                                                       \
    for (int _mt = 0; _mt < 4; _mt++) {                                     \
        const uint32_t* _ap = as + (warpM * 64 + _mt * 16 + g) * ASP        \
                                 + (ksv) * 8 + 2 * tig;                     \
        uint2 _u0 = *(const uint2*)_ap;                                     \
        uint2 _u8 = *(const uint2*)(_ap + 8 * ASP);                         \
        (afA)[_mt][0] = _u0.x; (afA)[_mt][1] = _u8.x;                       \
        (afA)[_mt][2] = _u0.y; (afA)[_mt][3] = _u8.y;                       \
    }                                                                       \
    _Pragma("unroll")                                                       \
    for (int _nt = 0; _nt < 4; _nt++)                                       \
        (bfA)[_nt] = *(const uint2*)(bs + ((ksv) * 4 + tig) * BSP           \
                                        + (warpN * 32 + _nt * 8 + g) * 2);  \
} while(0)

template<int EM>
__device__ __forceinline__ void gemm_body(
    const uint32_t* __restrict__ Ap, const uint32_t* __restrict__ Wp,
    const float* __restrict__ bias, void* __restrict__ C,
    int N, int K, int row0, int col0, uint32_t* sm)
{
    uint32_t* As0 = sm;
    uint32_t* Bs0 = As0 + 128 * ASP;
    uint32_t* As1 = Bs0 + 16 * BSP;
    uint32_t* Bs1 = As1 + 128 * ASP;

    const int tid  = threadIdx.x;
    const int lane = tid & 31;
    const int warp = tid >> 5;
    const int g    = lane >> 2;
    const int tig  = lane & 3;
    const int warpM = warp >> 2;
    const int warpN = warp & 3;

    float c[4][4][4];
    #pragma unroll
    for (int i = 0; i < 4; i++)
        #pragma unroll
        for (int j = 0; j < 4; j++)
            #pragma unroll
            for (int r = 0; r < 4; r++) c[i][j][r] = 0.0f;

    const int nk = K >> 5;
    const size_t wrow = (size_t)(2 * N);

    GSTAGE(As0, Bs0, 0);
    CP_COMMIT();

    for (int kt = 0; kt < nk; kt++) {
        CP_WAIT(0);
        __syncthreads();

        if (kt + 1 < nk) {
            if ((kt + 1) & 1) GSTAGE(As1, Bs1, kt + 1);
            else              GSTAGE(As0, Bs0, kt + 1);
            CP_COMMIT();
        }

        const uint32_t* as = (kt & 1) ? As1 : As0;
        const uint32_t* bs = (kt & 1) ? Bs1 : Bs0;

        uint32_t af[2][4][4];
        uint2    bf[2][4];
        GLOADFRAG(0, af[0], bf[0]);

        #pragma unroll
        for (int ks = 0; ks < 4; ks++) {
            const int cu = ks & 1;
            if (ks < 3) GLOADFRAG(ks + 1, af[cu ^ 1], bf[cu ^ 1]);
            #pragma unroll
            for (int mt = 0; mt < 4; mt++)
                #pragma unroll
                for (int nt = 0; nt < 4; nt++)
                    mma_tf32v(c[mt][nt], af[cu][mt], bf[cu][nt].x, bf[cu][nt].y);
        }
    }

    const int w0p = 4 * (tig & 1) + (tig >> 1);
    #pragma unroll
    for (int mt = 0; mt < 4; mt++) {
        const int r = row0 + warpM * 64 + mt * 16 + g;
        #pragma unroll
        for (int nt = 0; nt < 4; nt++) {
            const int cb = col0 + warpN * 32 + nt * 8;
            const float bv0 = bias[cb + 2 * tig];
            const float bv1 = bias[cb + 2 * tig + 1];
            if (EM == 0) {
                float* Cp = (float*)C;
                *(float2*)(Cp + (size_t)r * N + cb + 2 * tig) =
                    make_float2(c[mt][nt][0] + bv0, c[mt][nt][1] + bv1);
                *(float2*)(Cp + (size_t)(r + 8) * N + cb + 2 * tig) =
                    make_float2(c[mt][nt][2] + bv0, c[mt][nt][3] + bv1);
            } else if (EM == 1) {
                uint32_t* p0 = (uint32_t*)C + (size_t)r * N + cb;
                uint32_t* p8 = (uint32_t*)C + (size_t)(r + 8) * N + cb;
                p0[w0p]     = f2tf(c[mt][nt][0] + bv0);
                p0[w0p + 2] = f2tf(c[mt][nt][1] + bv1);
                p8[w0p]     = f2tf(c[mt][nt][2] + bv0);
                p8[w0p + 2] = f2tf(c[mt][nt][3] + bv1);
            } else {
                uint32_t* p0 = (uint32_t*)C + (size_t)r * N + cb + 2 * tig;
                uint32_t* p8 = (uint32_t*)C + (size_t)(r + 8) * N + cb + 2 * tig;
                *(uint2*)p0 = make_uint2(f2tf(c[mt][nt][0] + bv0),
                                         f2tf(c[mt][nt][1] + bv1));
                *(uint2*)p8 = make_uint2(f2tf(c[mt][nt][2] + bv0),
                                         f2tf(c[mt][nt][3] + bv1));
            }
        }
    }
}

__global__ void __launch_bounds__(256, 2) gemm_out_kernel(
    const uint32_t* __restrict__ Ap, const uint32_t* __restrict__ Wp,
    const float* __restrict__ bias, float* __restrict__ C, int N, int K)
{
    extern __shared__ uint32_t sm[];
    gemm_body<0>(Ap, Wp, bias, C, N, K, blockIdx.y * 128, blockIdx.x * 128, sm);
}

// Fused Q+K+V projections: Q,K -> tf32 paired; V -> tf32 natural.
__global__ void __launch_bounds__(256, 2) gemm_qkv_kernel(
    const uint32_t* __restrict__ xp,  const uint32_t* __restrict__ kvp,
    const uint32_t* __restrict__ wqp, const float* __restrict__ bq, uint32_t* __restrict__ q,
    const uint32_t* __restrict__ wkp, const float* __restrict__ bk, uint32_t* __restrict__ k,
    const uint32_t* __restrict__ wvp, const float* __restrict__ bv, uint32_t* __restrict__ v)
{
    extern __shared__ uint32_t sm[];
    const int bx = blockIdx.x;
    const int row0 = blockIdx.y * 128;
    if (bx < 16)
        gemm_body<1>(xp,  wqp, bq, q, DD,  DD, row0, bx * 128, sm);
    else if (bx < 20)
        gemm_body<1>(kvp, wkp, bk, k, KVD, DD, row0, (bx - 16) * 128, sm);
    else
        gemm_body<2>(kvp, wvp, bv, v, KVD, DD, row0, (bx - 20) * 128, sm);
}

// ---------------------------------------------------------------------------
// Fused causal GQA flash attention, TF32 MMA.
// 256 threads (8 warps x 16 q-rows), 128-row q-blocks, cp.async staging,
// inputs pre-converted to tf32 bits (Q/K paired, V natural) -> zero cvt here.
// ---------------------------------------------------------------------------
#define KST 72
#define VST 72
#define QST 72
#define PST 68
#define ATTN_SMEM_WORDS (64*KST + 64*VST + 128*QST + 128*PST)
#define ATTN_SMEM_BYTES (ATTN_SMEM_WORDS * 4)

__global__ void __launch_bounds__(256, 2) attn_tf32_kernel(
    const uint32_t* __restrict__ Q, const uint32_t* __restrict__ Kg,
    const uint32_t* __restrict__ Vg, float* __restrict__ O)
{
    extern __shared__ uint32_t smu[];
    uint32_t* Ks = smu;
    uint32_t* Vs = Ks + 64 * KST;
    uint32_t* Qs = Vs + 64 * VST;
    uint32_t* Ps = Qs + 128 * QST;

    const int tid  = threadIdx.x;
    const int lane = tid & 31;
    const int warp = tid >> 5;       // 0..7
    const int g    = lane >> 2;
    const int tig  = lane & 3;
    const int wr   = warp * 16;      // warp's q-row offset within the 128-block

    const int pr = blockIdx.x;       // pair index 0..7
    const int bh = blockIdx.y;
    const int b  = bh >> 5;
    const int h  = bh & 31;
    const int grp = h >> 2;

    const uint32_t* Qb = Q  + (size_t)(b * SS) * DD  + h * HD;
    const uint32_t* Kb = Kg + (size_t)(b * SS) * KVD + grp * HD;
    const uint32_t* Vb = Vg + (size_t)(b * SS) * KVD + grp * HD;

    for (int halfp = 0; halfp < 2; halfp++) {
        const int Qi = halfp ? (15 - pr) : pr;
        const int q0 = Qi * 128;

        __syncthreads();   // previous q-block fully consumed

        // stage Q: 128 rows x 64 words, pure cp.async (8 per thread)
        #pragma unroll
        for (int it = 0; it < 8; it++) {
            int idx = it * 256 + tid;
            int r = idx >> 4, c = (idx & 15) << 2;
            cpa16(sptr(Qs + r * QST + c), Qb + (size_t)(q0 + r) * DD + c);
        }
        CP_COMMIT();

        float o[8][4];
        float m0 = -1e30f, m1 = -1e30f, l0 = 0.0f, l1 = 0.0f;
        #pragma unroll
        for (int nt = 0; nt < 8; nt++)
            #pragma unroll
            for (int i = 0; i < 4; i++) o[nt][i] = 0.0f;

        const int tmax = 2 * Qi + 1;
        for (int t = 0; t <= tmax; t++) {
            const int k0 = t * 64;
            __syncthreads();   // all warps done reading prev Ks/Vs

            // stage K + V tiles (4+4 cp.async per thread)
            #pragma unroll
            for (int it = 0; it < 4; it++) {
                int idx = it * 256 + tid;
                int r = idx >> 4, c = (idx & 15) << 2;
                cpa16(sptr(Ks + r * KST + c), Kb + (size_t)(k0 + r) * KVD + c);
            }
            #pragma unroll
            for (int it = 0; it < 4; it++) {
                int idx = it * 256 + tid;
                int r = idx >> 4, c = (idx & 15) << 2;
                cpa16(sptr(Vs + r * VST + c), Vb + (size_t)(k0 + r) * KVD + c);
            }
            CP_COMMIT();
            CP_WAIT(0);
            __syncthreads();

            // S = Q @ K^T  (warp: 16 rows x 64 keys)
            float s[8][4];
            #pragma unroll
            for (int nt = 0; nt < 8; nt++)
                #pragma unroll
                for (int i = 0; i < 4; i++) s[nt][i] = 0.0f;

            #pragma unroll
            for (int ks = 0; ks < 8; ks++) {
                const uint32_t* qp = Qs + (wr + g) * QST + ks * 8 + 2 * tig;
                uint2 u0 = *(const uint2*)qp;
                uint2 u8 = *(const uint2*)(qp + 8 * QST);
                uint32_t af[4] = {u0.x, u8.x, u0.y, u8.y};
                #pragma unroll
                for (int nt = 0; nt < 8; nt++) {
                    uint2 kb = *(const uint2*)(Ks + (nt * 8 + g) * KST + ks * 8 + 2 * tig);
                    mma_tf32v(s[nt], af, kb.x, kb.y);
                }
            }

            // scale + causal mask
            const bool needmask = (k0 + 63 > q0 + wr);
            const int rowg = q0 + wr + g;
            #pragma unroll
            for (int nt = 0; nt < 8; nt++) {
                const int cbase = k0 + nt * 8 + 2 * tig;
                #pragma unroll
                for (int i = 0; i < 4; i++) {
                    float v = s[nt][i] * 0.125f;
                    if (needmask) {
                        int col = cbase + (i & 1);
                        int row = rowg + ((i & 2) ? 8 : 0);
                        if (col > row) v = -1e30f;
                    }
                    s[nt][i] = v;
                }
            }

            // online softmax (rows g, g+8)
            float r0 = -1e30f, r1 = -1e30f;
            #pragma unroll
            for (int nt = 0; nt < 8; nt++) {
                r0 = fmaxf(r0, fmaxf(s[nt][0], s[nt][1]));
                r1 = fmaxf(r1, fmaxf(s[nt][2], s[nt][3]));
            }
            r0 = fmaxf(r0, __shfl_xor_sync(0xffffffffu, r0, 1));
            r0 = fmaxf(r0, __shfl_xor_sync(0xffffffffu, r0, 2));
            r1 = fmaxf(r1, __shfl_xor_sync(0xffffffffu, r1, 1));
            r1 = fmaxf(r1, __shfl_xor_sync(0xffffffffu, r1, 2));

            const float mn0 = fmaxf(m0, r0), mn1 = fmaxf(m1, r1);
            const float e0 = __expf(m0 - mn0), e1 = __expf(m1 - mn1);
            m0 = mn0; m1 = mn1;

            float ls0 = 0.0f, ls1 = 0.0f;
            uint32_t* pbase = Ps + (wr + g) * PST;
            #pragma unroll
            for (int nt = 0; nt < 8; nt++) {
                o[nt][0] *= e0; o[nt][1] *= e0;
                o[nt][2] *= e1; o[nt][3] *= e1;
                float p0 = __expf(s[nt][0] - mn0);
                float p1 = __expf(s[nt][1] - mn0);
                float p2 = __expf(s[nt][2] - mn1);
                float p3 = __expf(s[nt][3] - mn1);
                ls0 += p0 + p1; ls1 += p2 + p3;
                uint32_t* pp = pbase + nt * 8 + 2 * tig;
                *(uint2*)pp             = make_uint2(f2tf(p0), f2tf(p1));
                *(uint2*)(pp + 8 * PST) = make_uint2(f2tf(p2), f2tf(p3));
            }
            ls0 += __shfl_xor_sync(0xffffffffu, ls0, 1);
            ls0 += __shfl_xor_sync(0xffffffffu, ls0, 2);
            ls1 += __shfl_xor_sync(0xffffffffu, ls1, 1);
            ls1 += __shfl_xor_sync(0xffffffffu, ls1, 2);
            l0 = l0 * e0 + ls0;
            l1 = l1 * e1 + ls1;

            __syncwarp();   // own-warp P rows written, reread below

            // O += P @ V
            #pragma unroll
            for (int ks = 0; ks < 8; ks++) {
                const uint32_t* pp = Ps + (wr + g) * PST + ks * 8 + tig;
                uint32_t pa[4];
                pa[0] = pp[0];
                pa[1] = pp[8 * PST];
                pa[2] = pp[4];
                pa[3] = pp[8 * PST + 4];
                #pragma unroll
                for (int nt = 0; nt < 8; nt++) {
                    const uint32_t* vp = Vs + (ks * 8 + tig) * VST + nt * 8 + g;
                    mma_tf32v(o[nt], pa, vp[0], vp[4 * VST]);
                }
            }
        }

        // epilogue: normalize, tf32-round, paired-row layout for Wo GEMM
        const int w0 = 4 * (tig & 1) + (tig >> 1);
        const float inv0 = 1.0f / l0, inv1 = 1.0f / l1;
        float* Ob = O + (size_t)(b * SS + q0 + wr + g) * DD + h * HD;
        #pragma unroll
        for (int nt = 0; nt < 8; nt++) {
            float* p0 = Ob + nt * 8;
            float* p8 = Ob + 8 * DD + nt * 8;
            p0[w0]     = __uint_as_float(f2tf(o[nt][0] * inv0));
            p0[w0 + 2] = __uint_as_float(f2tf(o[nt][1] * inv0));
            p8[w0]     = __uint_as_float(f2tf(o[nt][2] * inv1));
            p8[w0 + 2] = __uint_as_float(f2tf(o[nt][3] * inv1));
        }
    }
}

// ---------------------------------------------------------------------------
// Launch
// ---------------------------------------------------------------------------
extern "C" void kernel_launch(void* const* d_in, const int* in_sizes, int n_in,
                              void* d_out, int out_size)
{
    (void)in_sizes; (void)n_in; (void)out_size;
    const float* x  = (const float*)d_in[0];
    const float* kv = (const float*)d_in[1];
    const float* Wq = (const float*)d_in[2];
    const float* bq = (const float*)d_in[3];
    const float* Wk = (const float*)d_in[4];
    const float* bk = (const float*)d_in[5];
    const float* Wv = (const float*)d_in[6];
    const float* bv = (const float*)d_in[7];
    const float* Wo = (const float*)d_in[8];
    const float* bo = (const float*)d_in[9];
    float* out = (float*)d_out;

    uint32_t *q, *k, *v, *xp, *kvp, *wqp, *wkp, *wvp, *wop;
    float* ao;
    cudaGetSymbolAddress((void**)&q,   g_q);
    cudaGetSymbolAddress((void**)&k,   g_k);
    cudaGetSymbolAddress((void**)&v,   g_v);
    cudaGetSymbolAddress((void**)&ao,  g_ao);
    cudaGetSymbolAddress((void**)&xp,  g_xp);
    cudaGetSymbolAddress((void**)&kvp, g_kvp);
    cudaGetSymbolAddress((void**)&wqp, g_wqp);
    cudaGetSymbolAddress((void**)&wkp, g_wkp);
    cudaGetSymbolAddress((void**)&wvp, g_wvp);
    cudaGetSymbolAddress((void**)&wop, g_wop);

    cudaFuncSetAttribute(gemm_out_kernel,
                         cudaFuncAttributeMaxDynamicSharedMemorySize,
                         GEMM_SMEM_BYTES);
    cudaFuncSetAttribute(gemm_qkv_kernel,
                         cudaFuncAttributeMaxDynamicSharedMemorySize,
                         GEMM_SMEM_BYTES);
    cudaFuncSetAttribute(attn_tf32_kernel,
                         cudaFuncAttributeMaxDynamicSharedMemorySize,
                         ATTN_SMEM_BYTES);

    // pre-passes: tf32 convert + pair
    pair_rows_kernel<<<MTOT * DD / 8 / 256, 256>>>((const float4*)x,  (uint4*)xp);
    pair_rows_kernel<<<MTOT * DD / 8 / 256, 256>>>((const float4*)kv, (uint4*)kvp);
    pair_weights_kernel<<<(DD/2) * (DD/4)  / 256, 256>>>(Wq, wqp, DD);
    pair_weights_kernel<<<(DD/2) * (KVD/4) / 256, 256>>>(Wk, wkp, KVD);
    pair_weights_kernel<<<(DD/2) * (KVD/4) / 256, 256>>>(Wv, wvp, KVD);
    pair_weights_kernel<<<(DD/2) * (DD/4)  / 256, 256>>>(Wo, wop, DD);

    // fused Q+K+V projections -> tf32 outputs (Q/K paired, V natural)
    gemm_qkv_kernel<<<dim3(24, MTOT / 128), 256, GEMM_SMEM_BYTES>>>(
        xp, kvp, wqp, bq, q, wkp, bk, k, wvp, bv, v);

    // fused causal GQA attention (256 threads, cp.async staging, no cvt)
    attn_tf32_kernel<<<dim3(8, BB * HH), 256, ATTN_SMEM_BYTES>>>(q, k, v, ao);

    // output projection (consumes pre-paired tf32 ao directly)
    gemm_out_kernel<<<dim3(DD / 128, MTOT / 128), 256, GEMM_SMEM_BYTES>>>(
        (const uint32_t*)ao, wop, bo, out, DD, DD);
}

// round 10
// speedup vs baseline: 3.8727x; 1.0288x over previous
#include <cuda_runtime.h>
#include <math.h>
#include <stdint.h>

// Problem constants (fixed shapes)
#define BB 2
#define SS 2048
#define DD 2048
#define HH 32
#define GG 8
#define HD 64
#define KVD 512        // G*HD
#define MTOT (BB*SS)   // 4096

// Scratch (static device globals; no allocation allowed)
__device__ uint32_t g_q  [MTOT*DD];    // Q proj: tf32 bits, paired word order
__device__ uint32_t g_k  [MTOT*KVD];   // K proj: tf32 bits, paired word order
__device__ uint32_t g_v  [MTOT*KVD];   // V proj: tf32 bits, natural order
__device__ float    g_ao [MTOT*DD];    // attention out: tf32 bits, paired rows
__device__ uint32_t g_xp [MTOT*DD];    // x,  tf32 + paired rows
__device__ uint32_t g_kvp[MTOT*DD];    // kv, tf32 + paired rows
__device__ uint32_t g_wqp[DD*DD];      // weights: tf32, pair-row interleaved
__device__ uint32_t g_wkp[DD*KVD];
__device__ uint32_t g_wvp[DD*KVD];
__device__ uint32_t g_wop[DD*DD];

// ---------------------------------------------------------------------------
// helpers
// ---------------------------------------------------------------------------
__device__ __forceinline__ uint32_t f2tf(float x) {
    uint32_t r;
    asm("cvt.rna.tf32.f32 %0, %1;" : "=r"(r) : "f"(x));
    return r;
}
__device__ __forceinline__ uint32_t sptr(const void* p) {
    return (uint32_t)__cvta_generic_to_shared(p);
}
__device__ __forceinline__ void cpa16(uint32_t s, const void* g) {
    asm volatile("cp.async.cg.shared.global [%0], [%1], 16;" :: "r"(s), "l"(g));
}
#define CP_COMMIT() asm volatile("cp.async.commit_group;")
#define CP_WAIT(N)  asm volatile("cp.async.wait_group %0;" :: "n"(N))

__device__ __forceinline__ void mma_tf32(
    float& c0, float& c1, float& c2, float& c3,
    uint32_t a0, uint32_t a1, uint32_t a2, uint32_t a3,
    uint32_t b0, uint32_t b1)
{
    asm volatile(
        "mma.sync.aligned.m16n8k8.row.col.f32.tf32.tf32.f32 "
        "{%0,%1,%2,%3}, {%4,%5,%6,%7}, {%8,%9}, {%0,%1,%2,%3};"
        : "+f"(c0), "+f"(c1), "+f"(c2), "+f"(c3)
        : "r"(a0), "r"(a1), "r"(a2), "r"(a3), "r"(b0), "r"(b1));
}
__device__ __forceinline__ void mma_tf32v(float c[4], const uint32_t a[4],
                                          uint32_t b0, uint32_t b1)
{
    mma_tf32(c[0], c[1], c[2], c[3], a[0], a[1], a[2], a[3], b0, b1);
}

// ---------------------------------------------------------------------------
// Fused pre-pass: all tf32 conversions / re-layouts in ONE launch.
// Sections (in 256-item blocks):
//   x rows: 4096 | kv rows: 4096 | Wq: 2048 | Wk: 512 | Wv: 512 | Wo: 2048
// ---------------------------------------------------------------------------
__device__ __forceinline__ void do_pair_rows(
    const float4* __restrict__ in, uint4* __restrict__ out, int idx)
{
    const float4 v0 = in[idx * 2];
    const float4 v1 = in[idx * 2 + 1];
    out[idx * 2]     = make_uint4(f2tf(v0.x), f2tf(v1.x), f2tf(v0.y), f2tf(v1.y));
    out[idx * 2 + 1] = make_uint4(f2tf(v0.z), f2tf(v1.z), f2tf(v0.w), f2tf(v1.w));
}

__device__ __forceinline__ void do_pair_weights(
    const float* __restrict__ W, uint32_t* __restrict__ Wp, int N, int idx)
{
    const int ncq = N >> 2;
    const int p   = idx / ncq;
    const int nc  = idx - p * ncq;
    const int klo = (p >> 2) * 8 + (p & 3);
    const float4 lo = *(const float4*)(W + (size_t)klo * N + nc * 4);
    const float4 hi = *(const float4*)(W + (size_t)(klo + 4) * N + nc * 4);
    uint4* op = (uint4*)(Wp + (size_t)p * (2 * N) + nc * 8);
    op[0] = make_uint4(f2tf(lo.x), f2tf(hi.x), f2tf(lo.y), f2tf(hi.y));
    op[1] = make_uint4(f2tf(lo.z), f2tf(hi.z), f2tf(lo.w), f2tf(hi.w));
}

#define PB_X   4096
#define PB_KV  (PB_X  + 4096)
#define PB_WQ  (PB_KV + 2048)
#define PB_WK  (PB_WQ + 512)
#define PB_WV  (PB_WK + 512)
#define PB_WO  (PB_WV + 2048)   // total 13312 blocks

__global__ void __launch_bounds__(256) prepass_kernel(
    const float* __restrict__ x,  const float* __restrict__ kv,
    const float* __restrict__ Wq, const float* __restrict__ Wk,
    const float* __restrict__ Wv, const float* __restrict__ Wo,
    uint32_t* __restrict__ xp, uint32_t* __restrict__ kvp,
    uint32_t* __restrict__ wqp, uint32_t* __restrict__ wkp,
    uint32_t* __restrict__ wvp, uint32_t* __restrict__ wop)
{
    const int blk = blockIdx.x;
    if (blk < PB_X) {
        do_pair_rows((const float4*)x, (uint4*)xp, blk * 256 + threadIdx.x);
    } else if (blk < PB_KV) {
        do_pair_rows((const float4*)kv, (uint4*)kvp,
                     (blk - PB_X) * 256 + threadIdx.x);
    } else if (blk < PB_WQ) {
        do_pair_weights(Wq, wqp, DD,  (blk - PB_KV) * 256 + threadIdx.x);
    } else if (blk < PB_WK) {
        do_pair_weights(Wk, wkp, KVD, (blk - PB_WQ) * 256 + threadIdx.x);
    } else if (blk < PB_WV) {
        do_pair_weights(Wv, wvp, KVD, (blk - PB_WK) * 256 + threadIdx.x);
    } else {
        do_pair_weights(Wo, wop, DD,  (blk - PB_WV) * 256 + threadIdx.x);
    }
}

// ---------------------------------------------------------------------------
// TF32 GEMM + bias, templated epilogue:
//   EM=0: fp32 natural   EM=1: tf32 bits, paired word order   EM=2: tf32 natural
// Single __syncthreads per K-chunk; SINGLE-buffer fragments (no spills).
// ---------------------------------------------------------------------------
#define ASP 40
#define BSP 264
#define GEMM_BUF_WORDS (128*ASP + 16*BSP)
#define GEMM_SMEM_BYTES (2 * GEMM_BUF_WORDS * 4)

#define GSTAGE(asb, bsb, ktc) do {                                          \
    const int _kb = (ktc) << 5;                                             \
    const int _pg = (ktc) << 4;                                             \
    _Pragma("unroll")                                                       \
    for (int _it = 0; _it < 4; _it++) {                                     \
        int _idx = _it * 256 + tid;                                         \
        int _r = _idx >> 3, _w = (_idx & 7) << 2;                           \
        cpa16(sptr((asb) + _r * ASP + _w),                                  \
              Ap + (size_t)(row0 + _r) * K + _kb + _w);                     \
    }                                                                       \
    _Pragma("unroll")                                                       \
    for (int _it = 0; _it < 4; _it++) {                                     \
        int _idx = _it * 256 + tid;                                         \
        int _pr = _idx >> 6, _w = (_idx & 63) << 2;                         \
        cpa16(sptr((bsb) + _pr * BSP + _w),                                 \
              Wp + (size_t)(_pg + _pr) * wrow + col0 * 2 + _w);             \
    }                                                                       \
} while(0)

template<int EM>
__device__ __forceinline__ void gemm_body(
    const uint32_t* __restrict__ Ap, const uint32_t* __restrict__ Wp,
    const float* __restrict__ bias, void* __restrict__ C,
    int N, int K, int row0, int col0, uint32_t* sm)
{
    uint32_t* As0 = sm;
    uint32_t* Bs0 = As0 + 128 * ASP;
    uint32_t* As1 = Bs0 + 16 * BSP;
    uint32_t* Bs1 = As1 + 128 * ASP;

    const int tid  = threadIdx.x;
    const int lane = tid & 31;
    const int warp = tid >> 5;
    const int g    = lane >> 2;
    const int tig  = lane & 3;
    const int warpM = warp >> 2;
    const int warpN = warp & 3;

    float c[4][4][4];
    #pragma unroll
    for (int i = 0; i < 4; i++)
        #pragma unroll
        for (int j = 0; j < 4; j++)
            #pragma unroll
            for (int r = 0; r < 4; r++) c[i][j][r] = 0.0f;

    const int nk = K >> 5;
    const size_t wrow = (size_t)(2 * N);

    GSTAGE(As0, Bs0, 0);
    CP_COMMIT();

    for (int kt = 0; kt < nk; kt++) {
        CP_WAIT(0);
        __syncthreads();   // chunk kt visible; all warps done reading other buf

        if (kt + 1 < nk) {
            if ((kt + 1) & 1) GSTAGE(As1, Bs1, kt + 1);
            else              GSTAGE(As0, Bs0, kt + 1);
            CP_COMMIT();
        }

        const uint32_t* as = (kt & 1) ? As1 : As0;
        const uint32_t* bs = (kt & 1) ? Bs1 : Bs0;

        #pragma unroll
        for (int ks = 0; ks < 4; ks++) {
            uint32_t af[4][4];
            #pragma unroll
            for (int mt = 0; mt < 4; mt++) {
                const uint32_t* ap = as + (warpM * 64 + mt * 16 + g) * ASP
                                        + ks * 8 + 2 * tig;
                uint2 u0 = *(const uint2*)ap;
                uint2 u8 = *(const uint2*)(ap + 8 * ASP);
                af[mt][0] = u0.x; af[mt][1] = u8.x;
                af[mt][2] = u0.y; af[mt][3] = u8.y;
            }
            uint2 bf[4];
            #pragma unroll
            for (int nt = 0; nt < 4; nt++)
                bf[nt] = *(const uint2*)(bs + (ks * 4 + tig) * BSP
                                            + (warpN * 32 + nt * 8 + g) * 2);
            #pragma unroll
            for (int mt = 0; mt < 4; mt++)
                #pragma unroll
                for (int nt = 0; nt < 4; nt++)
                    mma_tf32v(c[mt][nt], af[mt], bf[nt].x, bf[nt].y);
        }
    }

    const int w0p = 4 * (tig & 1) + (tig >> 1);
    #pragma unroll
    for (int mt = 0; mt < 4; mt++) {
        const int r = row0 + warpM * 64 + mt * 16 + g;
        #pragma unroll
        for (int nt = 0; nt < 4; nt++) {
            const int cb = col0 + warpN * 32 + nt * 8;
            const float bv0 = bias[cb + 2 * tig];
            const float bv1 = bias[cb + 2 * tig + 1];
            if (EM == 0) {
                float* Cp = (float*)C;
                *(float2*)(Cp + (size_t)r * N + cb + 2 * tig) =
                    make_float2(c[mt][nt][0] + bv0, c[mt][nt][1] + bv1);
                *(float2*)(Cp + (size_t)(r + 8) * N + cb + 2 * tig) =
                    make_float2(c[mt][nt][2] + bv0, c[mt][nt][3] + bv1);
            } else if (EM == 1) {
                uint32_t* p0 = (uint32_t*)C + (size_t)r * N + cb;
                uint32_t* p8 = (uint32_t*)C + (size_t)(r + 8) * N + cb;
                p0[w0p]     = f2tf(c[mt][nt][0] + bv0);
                p0[w0p + 2] = f2tf(c[mt][nt][1] + bv1);
                p8[w0p]     = f2tf(c[mt][nt][2] + bv0);
                p8[w0p + 2] = f2tf(c[mt][nt][3] + bv1);
            } else {
                uint32_t* p0 = (uint32_t*)C + (size_t)r * N + cb + 2 * tig;
                uint32_t* p8 = (uint32_t*)C + (size_t)(r + 8) * N + cb + 2 * tig;
                *(uint2*)p0 = make_uint2(f2tf(c[mt][nt][0] + bv0),
                                         f2tf(c[mt][nt][1] + bv1));
                *(uint2*)p8 = make_uint2(f2tf(c[mt][nt][2] + bv0),
                                         f2tf(c[mt][nt][3] + bv1));
            }
        }
    }
}

__global__ void __launch_bounds__(256, 2) gemm_out_kernel(
    const uint32_t* __restrict__ Ap, const uint32_t* __restrict__ Wp,
    const float* __restrict__ bias, float* __restrict__ C, int N, int K)
{
    extern __shared__ uint32_t sm[];
    gemm_body<0>(Ap, Wp, bias, C, N, K, blockIdx.y * 128, blockIdx.x * 128, sm);
}

// Fused Q+K+V projections: Q,K -> tf32 paired; V -> tf32 natural.
__global__ void __launch_bounds__(256, 2) gemm_qkv_kernel(
    const uint32_t* __restrict__ xp,  const uint32_t* __restrict__ kvp,
    const uint32_t* __restrict__ wqp, const float* __restrict__ bq, uint32_t* __restrict__ q,
    const uint32_t* __restrict__ wkp, const float* __restrict__ bk, uint32_t* __restrict__ k,
    const uint32_t* __restrict__ wvp, const float* __restrict__ bv, uint32_t* __restrict__ v)
{
    extern __shared__ uint32_t sm[];
    const int bx = blockIdx.x;
    const int row0 = blockIdx.y * 128;
    if (bx < 16)
        gemm_body<1>(xp,  wqp, bq, q, DD,  DD, row0, bx * 128, sm);
    else if (bx < 20)
        gemm_body<1>(kvp, wkp, bk, k, KVD, DD, row0, (bx - 16) * 128, sm);
    else
        gemm_body<2>(kvp, wvp, bv, v, KVD, DD, row0, (bx - 20) * 128, sm);
}

// ---------------------------------------------------------------------------
// Fused causal GQA flash attention, TF32 MMA (unchanged from R8 971µs version).
// 256 threads (8 warps x 16 q-rows), 128-row q-blocks, cp.async staging.
// ---------------------------------------------------------------------------
#define KST 72
#define VST 72
#define QST 72
#define PST 68
#define ATTN_SMEM_WORDS (64*KST + 64*VST + 128*QST + 128*PST)
#define ATTN_SMEM_BYTES (ATTN_SMEM_WORDS * 4)

__global__ void __launch_bounds__(256, 2) attn_tf32_kernel(
    const uint32_t* __restrict__ Q, const uint32_t* __restrict__ Kg,
    const uint32_t* __restrict__ Vg, float* __restrict__ O)
{
    extern __shared__ uint32_t smu[];
    uint32_t* Ks = smu;
    uint32_t* Vs = Ks + 64 * KST;
    uint32_t* Qs = Vs + 64 * VST;
    uint32_t* Ps = Qs + 128 * QST;

    const int tid  = threadIdx.x;
    const int lane = tid & 31;
    const int warp = tid >> 5;
    const int g    = lane >> 2;
    const int tig  = lane & 3;
    const int wr   = warp * 16;

    const int pr = blockIdx.x;
    const int bh = blockIdx.y;
    const int b  = bh >> 5;
    const int h  = bh & 31;
    const int grp = h >> 2;

    const uint32_t* Qb = Q  + (size_t)(b * SS) * DD  + h * HD;
    const uint32_t* Kb = Kg + (size_t)(b * SS) * KVD + grp * HD;
    const uint32_t* Vb = Vg + (size_t)(b * SS) * KVD + grp * HD;

    for (int halfp = 0; halfp < 2; halfp++) {
        const int Qi = halfp ? (15 - pr) : pr;
        const int q0 = Qi * 128;

        __syncthreads();

        #pragma unroll
        for (int it = 0; it < 8; it++) {
            int idx = it * 256 + tid;
            int r = idx >> 4, c = (idx & 15) << 2;
            cpa16(sptr(Qs + r * QST + c), Qb + (size_t)(q0 + r) * DD + c);
        }
        CP_COMMIT();

        float o[8][4];
        float m0 = -1e30f, m1 = -1e30f, l0 = 0.0f, l1 = 0.0f;
        #pragma unroll
        for (int nt = 0; nt < 8; nt++)
            #pragma unroll
            for (int i = 0; i < 4; i++) o[nt][i] = 0.0f;

        const int tmax = 2 * Qi + 1;
        for (int t = 0; t <= tmax; t++) {
            const int k0 = t * 64;
            __syncthreads();

            #pragma unroll
            for (int it = 0; it < 4; it++) {
                int idx = it * 256 + tid;
                int r = idx >> 4, c = (idx & 15) << 2;
                cpa16(sptr(Ks + r * KST + c), Kb + (size_t)(k0 + r) * KVD + c);
            }
            #pragma unroll
            for (int it = 0; it < 4; it++) {
                int idx = it * 256 + tid;
                int r = idx >> 4, c = (idx & 15) << 2;
                cpa16(sptr(Vs + r * VST + c), Vb + (size_t)(k0 + r) * KVD + c);
            }
            CP_COMMIT();
            CP_WAIT(0);
            __syncthreads();

            float s[8][4];
            #pragma unroll
            for (int nt = 0; nt < 8; nt++)
                #pragma unroll
                for (int i = 0; i < 4; i++) s[nt][i] = 0.0f;

            #pragma unroll
            for (int ks = 0; ks < 8; ks++) {
                const uint32_t* qp = Qs + (wr + g) * QST + ks * 8 + 2 * tig;
                uint2 u0 = *(const uint2*)qp;
                uint2 u8 = *(const uint2*)(qp + 8 * QST);
                uint32_t af[4] = {u0.x, u8.x, u0.y, u8.y};
                #pragma unroll
                for (int nt = 0; nt < 8; nt++) {
                    uint2 kb = *(const uint2*)(Ks + (nt * 8 + g) * KST + ks * 8 + 2 * tig);
                    mma_tf32v(s[nt], af, kb.x, kb.y);
                }
            }

            const bool needmask = (k0 + 63 > q0 + wr);
            const int rowg = q0 + wr + g;
            #pragma unroll
            for (int nt = 0; nt < 8; nt++) {
                const int cbase = k0 + nt * 8 + 2 * tig;
                #pragma unroll
                for (int i = 0; i < 4; i++) {
                    float v = s[nt][i] * 0.125f;
                    if (needmask) {
                        int col = cbase + (i & 1);
                        int row = rowg + ((i & 2) ? 8 : 0);
                        if (col > row) v = -1e30f;
                    }
                    s[nt][i] = v;
                }
            }

            float r0 = -1e30f, r1 = -1e30f;
            #pragma unroll
            for (int nt = 0; nt < 8; nt++) {
                r0 = fmaxf(r0, fmaxf(s[nt][0], s[nt][1]));
                r1 = fmaxf(r1, fmaxf(s[nt][2], s[nt][3]));
            }
            r0 = fmaxf(r0, __shfl_xor_sync(0xffffffffu, r0, 1));
            r0 = fmaxf(r0, __shfl_xor_sync(0xffffffffu, r0, 2));
            r1 = fmaxf(r1, __shfl_xor_sync(0xffffffffu, r1, 1));
            r1 = fmaxf(r1, __shfl_xor_sync(0xffffffffu, r1, 2));

            const float mn0 = fmaxf(m0, r0), mn1 = fmaxf(m1, r1);
            const float e0 = __expf(m0 - mn0), e1 = __expf(m1 - mn1);
            m0 = mn0; m1 = mn1;

            float ls0 = 0.0f, ls1 = 0.0f;
            uint32_t* pbase = Ps + (wr + g) * PST;
            #pragma unroll
            for (int nt = 0; nt < 8; nt++) {
                o[nt][0] *= e0; o[nt][1] *= e0;
                o[nt][2] *= e1; o[nt][3] *= e1;
                float p0 = __expf(s[nt][0] - mn0);
                float p1 = __expf(s[nt][1] - mn0);
                float p2 = __expf(s[nt][2] - mn1);
                float p3 = __expf(s[nt][3] - mn1);
                ls0 += p0 + p1; ls1 += p2 + p3;
                uint32_t* pp = pbase + nt * 8 + 2 * tig;
                *(uint2*)pp             = make_uint2(f2tf(p0), f2tf(p1));
                *(uint2*)(pp + 8 * PST) = make_uint2(f2tf(p2), f2tf(p3));
            }
            ls0 += __shfl_xor_sync(0xffffffffu, ls0, 1);
            ls0 += __shfl_xor_sync(0xffffffffu, ls0, 2);
            ls1 += __shfl_xor_sync(0xffffffffu, ls1, 1);
            ls1 += __shfl_xor_sync(0xffffffffu, ls1, 2);
            l0 = l0 * e0 + ls0;
            l1 = l1 * e1 + ls1;

            __syncwarp();

            #pragma unroll
            for (int ks = 0; ks < 8; ks++) {
                const uint32_t* pp = Ps + (wr + g) * PST + ks * 8 + tig;
                uint32_t pa[4];
                pa[0] = pp[0];
                pa[1] = pp[8 * PST];
                pa[2] = pp[4];
                pa[3] = pp[8 * PST + 4];
                #pragma unroll
                for (int nt = 0; nt < 8; nt++) {
                    const uint32_t* vp = Vs + (ks * 8 + tig) * VST + nt * 8 + g;
                    mma_tf32v(o[nt], pa, vp[0], vp[4 * VST]);
                }
            }
        }

        const int w0 = 4 * (tig & 1) + (tig >> 1);
        const float inv0 = 1.0f / l0, inv1 = 1.0f / l1;
        float* Ob = O + (size_t)(b * SS + q0 + wr + g) * DD + h * HD;
        #pragma unroll
        for (int nt = 0; nt < 8; nt++) {
            float* p0 = Ob + nt * 8;
            float* p8 = Ob + 8 * DD + nt * 8;
            p0[w0]     = __uint_as_float(f2tf(o[nt][0] * inv0));
            p0[w0 + 2] = __uint_as_float(f2tf(o[nt][1] * inv0));
            p8[w0]     = __uint_as_float(f2tf(o[nt][2] * inv1));
            p8[w0 + 2] = __uint_as_float(f2tf(o[nt][3] * inv1));
        }
    }
}

// ---------------------------------------------------------------------------
// Launch
// ---------------------------------------------------------------------------
extern "C" void kernel_launch(void* const* d_in, const int* in_sizes, int n_in,
                              void* d_out, int out_size)
{
    (void)in_sizes; (void)n_in; (void)out_size;
    const float* x  = (const float*)d_in[0];
    const float* kv = (const float*)d_in[1];
    const float* Wq = (const float*)d_in[2];
    const float* bq = (const float*)d_in[3];
    const float* Wk = (const float*)d_in[4];
    const float* bk = (const float*)d_in[5];
    const float* Wv = (const float*)d_in[6];
    const float* bv = (const float*)d_in[7];
    const float* Wo = (const float*)d_in[8];
    const float* bo = (const float*)d_in[9];
    float* out = (float*)d_out;

    uint32_t *q, *k, *v, *xp, *kvp, *wqp, *wkp, *wvp, *wop;
    float* ao;
    cudaGetSymbolAddress((void**)&q,   g_q);
    cudaGetSymbolAddress((void**)&k,   g_k);
    cudaGetSymbolAddress((void**)&v,   g_v);
    cudaGetSymbolAddress((void**)&ao,  g_ao);
    cudaGetSymbolAddress((void**)&xp,  g_xp);
    cudaGetSymbolAddress((void**)&kvp, g_kvp);
    cudaGetSymbolAddress((void**)&wqp, g_wqp);
    cudaGetSymbolAddress((void**)&wkp, g_wkp);
    cudaGetSymbolAddress((void**)&wvp, g_wvp);
    cudaGetSymbolAddress((void**)&wop, g_wop);

    cudaFuncSetAttribute(gemm_out_kernel,
                         cudaFuncAttributeMaxDynamicSharedMemorySize,
                         GEMM_SMEM_BYTES);
    cudaFuncSetAttribute(gemm_qkv_kernel,
                         cudaFuncAttributeMaxDynamicSharedMemorySize,
                         GEMM_SMEM_BYTES);
    cudaFuncSetAttribute(attn_tf32_kernel,
                         cudaFuncAttributeMaxDynamicSharedMemorySize,
                         ATTN_SMEM_BYTES);

    // single fused pre-pass (all tf32 conversions + re-layouts)
    prepass_kernel<<<PB_WO, 256>>>(x, kv, Wq, Wk, Wv, Wo,
                                   xp, kvp, wqp, wkp, wvp, wop);

    // fused Q+K+V projections -> tf32 outputs (Q/K paired, V natural)
    gemm_qkv_kernel<<<dim3(24, MTOT / 128), 256, GEMM_SMEM_BYTES>>>(
        xp, kvp, wqp, bq, q, wkp, bk, k, wvp, bv, v);

    // fused causal GQA attention
    attn_tf32_kernel<<<dim3(8, BB * HH), 256, ATTN_SMEM_BYTES>>>(q, k, v, ao);

    // output projection (consumes pre-paired tf32 ao directly)
    gemm_out_kernel<<<dim3(DD / 128, MTOT / 128), 256, GEMM_SMEM_BYTES>>>(
        (const uint32_t*)ao, wop, bo, out, DD, DD);
}